// round 9
// baseline (speedup 1.0000x reference)
#include <cuda_runtime.h>
#include <cuda_bf16.h>
#include <math.h>
#include <float.h>
#include <stdint.h>

#define B_    2
#define S_    2048
#define DIM_  2048
#define H_    16
#define KVH_  4
#define HD_   128
#define G_    4
#define M_    (B_*S_)          // 4096 rows total
#define QD_   (H_*HD_)         // 2048
#define KD_   (KVH_*HD_)       // 512

// ---------------------------------------------------------------------------
// Scratch (device globals -- no allocation). bf16 data held as u32 = bf16x2.
// ---------------------------------------------------------------------------
__device__ __align__(16) unsigned g_xhi [(size_t)M_*DIM_/2];
__device__ __align__(16) unsigned g_xlo [(size_t)M_*DIM_/2];
__device__ __align__(16) unsigned g_wqhi[(size_t)QD_*DIM_/2];
__device__ __align__(16) unsigned g_wqlo[(size_t)QD_*DIM_/2];
__device__ __align__(16) unsigned g_wkhi[(size_t)KD_*DIM_/2];
__device__ __align__(16) unsigned g_wklo[(size_t)KD_*DIM_/2];
__device__ __align__(16) unsigned g_wvhi[(size_t)KD_*DIM_/2];
__device__ __align__(16) unsigned g_wvlo[(size_t)KD_*DIM_/2];
__device__ __align__(16) unsigned g_wohi[(size_t)DIM_*QD_/2];
__device__ __align__(16) unsigned g_wolo[(size_t)DIM_*QD_/2];
__device__ __align__(16) unsigned g_qhi [(size_t)M_*QD_/2];
__device__ __align__(16) unsigned g_qlo [(size_t)M_*QD_/2];
__device__ __align__(16) unsigned g_khi [(size_t)M_*KD_/2];
__device__ __align__(16) unsigned g_klo [(size_t)M_*KD_/2];
__device__ __align__(16) unsigned g_vhi [(size_t)M_*KD_/2];
__device__ __align__(16) unsigned g_vlo [(size_t)M_*KD_/2];
__device__ __align__(16) unsigned g_athi[(size_t)M_*QD_/2];
__device__ __align__(16) unsigned g_atlo[(size_t)M_*QD_/2];

// ---------------------------------------------------------------------------
// helpers
// ---------------------------------------------------------------------------
__device__ __forceinline__ void cp_async16(unsigned saddr, const void* gptr) {
    asm volatile("cp.async.cg.shared.global [%0], [%1], 16;" :: "r"(saddr), "l"(gptr));
}
// pack two floats into bf16x2: low half = first arg, high half = second arg
__device__ __forceinline__ unsigned pk2(float lo_elem, float hi_elem) {
    unsigned d;
    asm("cvt.rn.bf16x2.f32 %0, %1, %2;" : "=r"(d) : "f"(hi_elem), "f"(lo_elem));
    return d;
}
__device__ __forceinline__ float blo(unsigned u) { return __uint_as_float(u << 16); }
__device__ __forceinline__ float bhi(unsigned u) { return __uint_as_float(u & 0xffff0000u); }

#define MMA_BF16(d, a0, a1, a2, a3, b0, b1) \
    asm volatile("mma.sync.aligned.m16n8k16.row.col.f32.bf16.bf16.f32 " \
                 "{%0,%1,%2,%3},{%4,%5,%6,%7},{%8,%9},{%0,%1,%2,%3};" \
                 : "+f"(d[0]), "+f"(d[1]), "+f"(d[2]), "+f"(d[3]) \
                 : "r"(a0), "r"(a1), "r"(a2), "r"(a3), "r"(b0), "r"(b1))

#define LDSM4(r0, r1, r2, r3, addr) \
    asm volatile("ldmatrix.sync.aligned.m8n8.x4.shared.b16 {%0,%1,%2,%3}, [%4];" \
                 : "=r"(r0), "=r"(r1), "=r"(r2), "=r"(r3) : "r"(addr))

// ---------------------------------------------------------------------------
// fp32 -> bf16 hi/lo split (elementwise)
// ---------------------------------------------------------------------------
__global__ void split_kernel(const float4* __restrict__ src,
                             uint2* __restrict__ hi, uint2* __restrict__ lo, int n4)
{
    int i = blockIdx.x * blockDim.x + threadIdx.x;
    if (i >= n4) return;
    float4 f = src[i];
    unsigned h0 = pk2(f.x, f.y), h1 = pk2(f.z, f.w);
    hi[i] = make_uint2(h0, h1);
    lo[i] = make_uint2(pk2(f.x - blo(h0), f.y - bhi(h0)),
                       pk2(f.z - blo(h1), f.w - bhi(h1)));
}

// ---------------------------------------------------------------------------
// bf16x3 mma.sync GEMM on pre-split operands: C[M,N] = A[M,K] * W[N,K]^T.
// Block 128x128, 8 warps (2x4), warp tile 64x32, k-block 32 bf16.
// 2-stage cp.async pipeline; ldmatrix.x4 fragment loads; zero conversions in
// the main loop. Row stride 80B => conflict-free ldmatrix.
// Output: fp32 C (Cf) OR hi/lo split (Chi/Clo); optional fused RoPE.
// ---------------------------------------------------------------------------
#define RSB_     80          // bytes per smem row (64 data + 16 pad)
#define ARRB_    10240       // bytes per array per stage (128 * 80)
#define STAGEB_  40960       // 4 arrays
#define GEMM_SMEM (2 * STAGEB_)

__global__ __launch_bounds__(256, 2) void gemm_mma_bf16x3(
    const unsigned* __restrict__ Ahi, const unsigned* __restrict__ Alo,
    const unsigned* __restrict__ Bhi, const unsigned* __restrict__ Blo,
    float* __restrict__ Cf, unsigned* __restrict__ Chi, unsigned* __restrict__ Clo,
    int Nn, int Kn, int do_rope, const float* __restrict__ freqs)
{
    extern __shared__ char gsm[];
    const unsigned smb = (unsigned)__cvta_generic_to_shared(gsm);

    const int tid  = threadIdx.x;
    const int lane = tid & 31;
    const int warp = tid >> 5;
    const int warpM = (warp >> 2) * 64;   // 0 or 64
    const int warpN = (warp & 3) * 32;    // 0,32,64,96
    const int r = lane >> 2;              // 0..7
    const int c = lane & 3;               // 0..3
    const int grp = lane >> 3;            // 0..3 (ldmatrix matrix select)
    const int lr  = lane & 7;             // row within 8
    const int m0 = blockIdx.y * 128;
    const int n0 = blockIdx.x * 128;
    const int NB = Kn >> 5;               // 32-wide k-blocks

    const char* Ah = (const char*)Ahi;
    const char* Al = (const char*)Alo;
    const char* Bh = (const char*)Bhi;
    const char* Bl = (const char*)Blo;
    const size_t rowb = (size_t)Kn * 2;   // bytes per global row

    float acc[4][4][4];
#pragma unroll
    for (int i = 0; i < 4; ++i)
#pragma unroll
        for (int j = 0; j < 4; ++j)
#pragma unroll
            for (int t = 0; t < 4; ++t) acc[i][j][t] = 0.f;

    const int lrow = tid >> 2;            // 0..63
    const int lc16 = tid & 3;

    auto load_block = [&](int kb, int p) {
        unsigned sb = smb + (unsigned)p * STAGEB_;
        size_t koff = (size_t)kb * 64 + lc16 * 16;
#pragma unroll
        for (int i = 0; i < 8; ++i) {
            const int arr = i >> 1;                 // 0..3 (compile-time)
            int row = (i & 1) * 64 + lrow;
            unsigned sa = sb + arr * ARRB_ + row * RSB_ + lc16 * 16;
            const char* g =
                (arr == 0) ? Ah + (size_t)(m0 + row) * rowb + koff :
                (arr == 1) ? Al + (size_t)(m0 + row) * rowb + koff :
                (arr == 2) ? Bh + (size_t)(n0 + row) * rowb + koff :
                             Bl + (size_t)(n0 + row) * rowb + koff;
            cp_async16(sa, g);
        }
        asm volatile("cp.async.commit_group;" ::: "memory");
    };

    load_block(0, 0);

    for (int kb = 0; kb < NB; ++kb) {
        const int p = kb & 1;
        if (kb + 1 < NB) {
            load_block(kb + 1, p ^ 1);
            asm volatile("cp.async.wait_group 1;" ::: "memory");
        } else {
            asm volatile("cp.async.wait_group 0;" ::: "memory");
        }
        __syncthreads();

        unsigned sb = smb + (unsigned)p * STAGEB_;
#pragma unroll
        for (int kk = 0; kk < 2; ++kk) {
            // B fragments for 4 n-subtiles (pairs), hi and lo
            unsigned bhf[2][4], blf[2][4];
#pragma unroll
            for (int bp = 0; bp < 2; ++bp) {
                unsigned baddr = sb + 2 * ARRB_ +
                    (unsigned)((warpN + bp * 16 + (grp >> 1) * 8 + lr) * RSB_ + kk * 32 + (grp & 1) * 16);
                LDSM4(bhf[bp][0], bhf[bp][1], bhf[bp][2], bhf[bp][3], baddr);
                LDSM4(blf[bp][0], blf[bp][1], blf[bp][2], blf[bp][3], baddr + ARRB_);
            }
#pragma unroll
            for (int am = 0; am < 4; ++am) {
                unsigned aaddr = sb +
                    (unsigned)((warpM + am * 16 + (grp & 1) * 8 + lr) * RSB_ + kk * 32 + (grp >> 1) * 16);
                unsigned ah0, ah1, ah2, ah3, al0, al1, al2, al3;
                LDSM4(ah0, ah1, ah2, ah3, aaddr);
                LDSM4(al0, al1, al2, al3, aaddr + ARRB_);
#pragma unroll
                for (int bn = 0; bn < 4; ++bn) {
                    const int bp = bn >> 1, off = (bn & 1) * 2;
                    MMA_BF16(acc[am][bn], ah0, ah1, ah2, ah3, bhf[bp][off], bhf[bp][off + 1]);
                    MMA_BF16(acc[am][bn], ah0, ah1, ah2, ah3, blf[bp][off], blf[bp][off + 1]);
                    MMA_BF16(acc[am][bn], al0, al1, al2, al3, bhf[bp][off], bhf[bp][off + 1]);
                }
            }
        }
        __syncthreads();
    }

    // ---- epilogue: optional RoPE, then fp32 or hi/lo-split store ----
#pragma unroll
    for (int am = 0; am < 4; ++am) {
#pragma unroll
        for (int bn = 0; bn < 4; ++bn) {
            int n1 = n0 + warpN + bn * 8 + 2 * c;
#pragma unroll
            for (int half = 0; half < 2; ++half) {
                int m1 = m0 + warpM + am * 16 + r + half * 8;
                float2 v = make_float2(acc[am][bn][2 * half], acc[am][bn][2 * half + 1]);
                if (do_rope) {
                    int j = (n1 & (HD_ - 1)) >> 1;
                    int s = m1 & (S_ - 1);
                    float2 cs = *(const float2*)&freqs[((size_t)s * 64 + j) * 2];
                    v = make_float2(v.x * cs.x - v.y * cs.y,
                                    v.x * cs.y + v.y * cs.x);
                }
                if (Cf) {
                    *(float2*)&Cf[(size_t)m1 * Nn + n1] = v;
                } else {
                    size_t w = (size_t)m1 * (Nn >> 1) + (n1 >> 1);
                    unsigned h = pk2(v.x, v.y);
                    Chi[w] = h;
                    Clo[w] = pk2(v.x - blo(h), v.y - bhi(h));
                }
            }
        }
    }
}

// ---------------------------------------------------------------------------
// Flash attention, bf16x3 mma.sync (causal, GQA). Inputs pre-split hi/lo;
// smem fill is a pure copy. Output written as split athi/atlo for WO GEMM.
// ---------------------------------------------------------------------------
#define QHI_OFF 0
#define QLO_OFF 8704
#define KHI_OFF 17408
#define KLO_OFF 21760
#define VHI_OFF 26112
#define VLO_OFF 30464
#define FLASH_SMEM_WORDS 34816

__global__ __launch_bounds__(256, 1) void flash_bf16_kernel(
    const unsigned* __restrict__ QHIg, const unsigned* __restrict__ QLOg,
    const unsigned* __restrict__ KHIg, const unsigned* __restrict__ KLOg,
    const unsigned* __restrict__ VHIg, const unsigned* __restrict__ VLOg,
    unsigned* __restrict__ OHI, unsigned* __restrict__ OLO)
{
    extern __shared__ unsigned smw[];
    unsigned* QHI = smw + QHI_OFF;
    unsigned* QLO = smw + QLO_OFF;
    unsigned* KHI = smw + KHI_OFF;
    unsigned* KLO = smw + KLO_OFF;
    unsigned* VHI = smw + VHI_OFF;
    unsigned* VLO = smw + VLO_OFF;
    const unsigned smb = (unsigned)__cvta_generic_to_shared(smw);

    const int bh = blockIdx.x;
    const int ib = (int)gridDim.y - 1 - (int)blockIdx.y;  // heavy tiles first
    const int b  = bh / H_;
    const int h  = bh % H_;
    const int kv = h / G_;

    const int tid  = threadIdx.x;
    const int lane = tid & 31;
    const int warp = tid >> 5;
    const int r = lane >> 2;
    const int c = lane & 3;
    const float scale = 0.08838834764831845f;

    // ---- Q tile (128 rows x 64 words) copy ----
    for (int i = tid; i < 128 * 32; i += 256) {
        int row = i >> 5, w2 = (i & 31) * 2;
        size_t gw = (size_t)(b * S_ + ib * 128 + row) * (QD_ / 2) + h * 64 + w2;
        uint2 hv = *(const uint2*)&QHIg[gw];
        uint2 lv = *(const uint2*)&QLOg[gw];
        int w = row * 68 + w2;
        QHI[w] = hv.x; QHI[w + 1] = hv.y;
        QLO[w] = lv.x; QLO[w + 1] = lv.y;
    }

    float m0 = -1e30f, m1 = -1e30f, l0s = 0.f, l1s = 0.f;
    float acc[16][4];
#pragma unroll
    for (int t = 0; t < 16; ++t)
#pragma unroll
        for (int e = 0; e < 4; ++e) acc[t][e] = 0.f;

    const int qr0 = ib * 128 + warp * 16 + r;
    const int qr1 = qr0 + 8;
    const int jmax = 2 * ib + 1;

    for (int j = 0; j <= jmax; ++j) {
        __syncthreads();
        // ---- K/V tile (64 rows x 64 words each) copy ----
        for (int i = tid; i < 64 * 32; i += 256) {
            int row = i >> 5, w2 = (i & 31) * 2;
            size_t gw = (size_t)(b * S_ + j * 64 + row) * (KD_ / 2) + kv * 64 + w2;
            int w = row * 68 + w2;
            uint2 khv = *(const uint2*)&KHIg[gw];
            uint2 klv = *(const uint2*)&KLOg[gw];
            KHI[w] = khv.x; KHI[w + 1] = khv.y;
            KLO[w] = klv.x; KLO[w + 1] = klv.y;
            uint2 vhv = *(const uint2*)&VHIg[gw];
            uint2 vlv = *(const uint2*)&VLOg[gw];
            VHI[w] = vhv.x; VHI[w + 1] = vhv.y;
            VLO[w] = vlv.x; VLO[w + 1] = vlv.y;
        }
        __syncthreads();

        // ---- QK^T ----
        float s[8][4];
#pragma unroll
        for (int bn = 0; bn < 8; ++bn)
#pragma unroll
            for (int e = 0; e < 4; ++e) s[bn][e] = 0.f;

#pragma unroll
        for (int kk = 0; kk < 8; ++kk) {
            int a0i = (warp * 16 + r) * 68 + kk * 8 + c;
            int a1i = a0i + 8 * 68;
            unsigned ah0 = QHI[a0i], ah1 = QHI[a1i], ah2 = QHI[a0i + 4], ah3 = QHI[a1i + 4];
            unsigned al0 = QLO[a0i], al1 = QLO[a1i], al2 = QLO[a0i + 4], al3 = QLO[a1i + 4];
#pragma unroll
            for (int bn = 0; bn < 8; ++bn) {
                int bi = (bn * 8 + r) * 68 + kk * 8 + c;
                unsigned kb0 = KHI[bi], kb1 = KHI[bi + 4];
                unsigned kl0 = KLO[bi], kl1 = KLO[bi + 4];
                MMA_BF16(s[bn], ah0, ah1, ah2, ah3, kb0, kb1);
                MMA_BF16(s[bn], ah0, ah1, ah2, ah3, kl0, kl1);
                MMA_BF16(s[bn], al0, al1, al2, al3, kb0, kb1);
            }
        }

        // ---- scale, mask, online softmax ----
        const bool need_mask = (j >= 2 * ib);
        float vmax0 = -1e30f, vmax1 = -1e30f;
#pragma unroll
        for (int bn = 0; bn < 8; ++bn) {
#pragma unroll
            for (int e = 0; e < 2; ++e) {
                int col = j * 64 + bn * 8 + 2 * c + e;
                float v0 = s[bn][e] * scale;
                if (need_mask && col > qr0) v0 = -1e30f;
                s[bn][e] = v0;
                vmax0 = fmaxf(vmax0, v0);
                float v1 = s[bn][2 + e] * scale;
                if (need_mask && col > qr1) v1 = -1e30f;
                s[bn][2 + e] = v1;
                vmax1 = fmaxf(vmax1, v1);
            }
        }
        vmax0 = fmaxf(vmax0, __shfl_xor_sync(0xffffffffu, vmax0, 1));
        vmax0 = fmaxf(vmax0, __shfl_xor_sync(0xffffffffu, vmax0, 2));
        vmax1 = fmaxf(vmax1, __shfl_xor_sync(0xffffffffu, vmax1, 1));
        vmax1 = fmaxf(vmax1, __shfl_xor_sync(0xffffffffu, vmax1, 2));

        float mn0 = fmaxf(m0, vmax0), mn1 = fmaxf(m1, vmax1);
        float alpha0 = __expf(m0 - mn0), alpha1 = __expf(m1 - mn1);
        m0 = mn0; m1 = mn1;

        float rs0 = 0.f, rs1 = 0.f;
#pragma unroll
        for (int bn = 0; bn < 8; ++bn) {
#pragma unroll
            for (int e = 0; e < 2; ++e) {
                float p0 = __expf(s[bn][e] - mn0);
                s[bn][e] = p0; rs0 += p0;
                float p1 = __expf(s[bn][2 + e] - mn1);
                s[bn][2 + e] = p1; rs1 += p1;
            }
        }
        rs0 += __shfl_xor_sync(0xffffffffu, rs0, 1);
        rs0 += __shfl_xor_sync(0xffffffffu, rs0, 2);
        rs1 += __shfl_xor_sync(0xffffffffu, rs1, 1);
        rs1 += __shfl_xor_sync(0xffffffffu, rs1, 2);
        l0s = l0s * alpha0 + rs0;
        l1s = l1s * alpha1 + rs1;

#pragma unroll
        for (int t = 0; t < 16; ++t) {
            acc[t][0] *= alpha0; acc[t][1] *= alpha0;
            acc[t][2] *= alpha1; acc[t][3] *= alpha1;
        }

        // ---- PV ----
#pragma unroll
        for (int kk = 0; kk < 4; ++kk) {
            unsigned ph0 = pk2(s[2 * kk][0], s[2 * kk][1]);
            unsigned ph1 = pk2(s[2 * kk][2], s[2 * kk][3]);
            unsigned ph2 = pk2(s[2 * kk + 1][0], s[2 * kk + 1][1]);
            unsigned ph3 = pk2(s[2 * kk + 1][2], s[2 * kk + 1][3]);
            unsigned pl0 = pk2(s[2 * kk][0] - blo(ph0), s[2 * kk][1] - bhi(ph0));
            unsigned pl1 = pk2(s[2 * kk][2] - blo(ph1), s[2 * kk][3] - bhi(ph1));
            unsigned pl2 = pk2(s[2 * kk + 1][0] - blo(ph2), s[2 * kk + 1][1] - bhi(ph2));
            unsigned pl3 = pk2(s[2 * kk + 1][2] - blo(ph3), s[2 * kk + 1][3] - bhi(ph3));

            int sel = lane >> 3;
            int lrw = lane & 7;
            int vrow = kk * 16 + (sel & 1) * 8 + lrw;
            int coff = (sel >> 1) * 8;

#pragma unroll
            for (int t = 0; t < 16; t += 2) {
                unsigned addr_h = smb + VHI_OFF * 4u + (unsigned)(vrow * 272 + (t * 8 + coff) * 2);
                unsigned addr_l = smb + VLO_OFF * 4u + (unsigned)(vrow * 272 + (t * 8 + coff) * 2);
                unsigned vh0, vh1, vh2, vh3, vl0, vl1, vl2, vl3;
                asm volatile("ldmatrix.sync.aligned.m8n8.x4.trans.shared.b16 {%0,%1,%2,%3}, [%4];"
                             : "=r"(vh0), "=r"(vh1), "=r"(vh2), "=r"(vh3) : "r"(addr_h));
                asm volatile("ldmatrix.sync.aligned.m8n8.x4.trans.shared.b16 {%0,%1,%2,%3}, [%4];"
                             : "=r"(vl0), "=r"(vl1), "=r"(vl2), "=r"(vl3) : "r"(addr_l));
                MMA_BF16(acc[t],     ph0, ph1, ph2, ph3, vh0, vh1);
                MMA_BF16(acc[t],     ph0, ph1, ph2, ph3, vl0, vl1);
                MMA_BF16(acc[t],     pl0, pl1, pl2, pl3, vh0, vh1);
                MMA_BF16(acc[t + 1], ph0, ph1, ph2, ph3, vh2, vh3);
                MMA_BF16(acc[t + 1], ph0, ph1, ph2, ph3, vl2, vl3);
                MMA_BF16(acc[t + 1], pl0, pl1, pl2, pl3, vh2, vh3);
            }
        }
    }

    // ---- epilogue: write attn as bf16 hi/lo (word layout [row][QD_/2]) ----
    float inv0 = 1.f / l0s, inv1 = 1.f / l1s;
#pragma unroll
    for (int t = 0; t < 16; ++t) {
        size_t w0 = (size_t)(b * S_ + qr0) * (QD_ / 2) + h * 64 + t * 4 + c;
        size_t w1 = (size_t)(b * S_ + qr1) * (QD_ / 2) + h * 64 + t * 4 + c;
        float a0 = acc[t][0] * inv0, a1 = acc[t][1] * inv0;
        float a2 = acc[t][2] * inv1, a3 = acc[t][3] * inv1;
        unsigned h0 = pk2(a0, a1);
        unsigned h1 = pk2(a2, a3);
        OHI[w0] = h0;
        OLO[w0] = pk2(a0 - blo(h0), a1 - bhi(h0));
        OHI[w1] = h1;
        OLO[w1] = pk2(a2 - blo(h1), a3 - bhi(h1));
    }
}

// ---------------------------------------------------------------------------
extern "C" void kernel_launch(void* const* d_in, const int* in_sizes, int n_in,
                              void* d_out, int out_size)
{
    const float* x     = (const float*)d_in[0];
    const float* freqs = (const float*)d_in[1];
    const float* wq    = (const float*)d_in[2];
    const float* wk    = (const float*)d_in[3];
    const float* wv    = (const float*)d_in[4];
    const float* wo    = (const float*)d_in[5];
    float* out = (float*)d_out;

    unsigned *xhi, *xlo, *wqhi, *wqlo, *wkhi, *wklo, *wvhi, *wvlo, *wohi, *wolo;
    unsigned *qhi, *qlo, *khi, *klo, *vhi, *vlo, *athi, *atlo;
    cudaGetSymbolAddress((void**)&xhi,  g_xhi);
    cudaGetSymbolAddress((void**)&xlo,  g_xlo);
    cudaGetSymbolAddress((void**)&wqhi, g_wqhi);
    cudaGetSymbolAddress((void**)&wqlo, g_wqlo);
    cudaGetSymbolAddress((void**)&wkhi, g_wkhi);
    cudaGetSymbolAddress((void**)&wklo, g_wklo);
    cudaGetSymbolAddress((void**)&wvhi, g_wvhi);
    cudaGetSymbolAddress((void**)&wvlo, g_wvlo);
    cudaGetSymbolAddress((void**)&wohi, g_wohi);
    cudaGetSymbolAddress((void**)&wolo, g_wolo);
    cudaGetSymbolAddress((void**)&qhi,  g_qhi);
    cudaGetSymbolAddress((void**)&qlo,  g_qlo);
    cudaGetSymbolAddress((void**)&khi,  g_khi);
    cudaGetSymbolAddress((void**)&klo,  g_klo);
    cudaGetSymbolAddress((void**)&vhi,  g_vhi);
    cudaGetSymbolAddress((void**)&vlo,  g_vlo);
    cudaGetSymbolAddress((void**)&athi, g_athi);
    cudaGetSymbolAddress((void**)&atlo, g_atlo);

    static int attr_set = 0;
    const int flash_smem = FLASH_SMEM_WORDS * 4;  // 139264
    if (!attr_set) {
        cudaFuncSetAttribute(gemm_mma_bf16x3,
                             cudaFuncAttributeMaxDynamicSharedMemorySize, GEMM_SMEM);
        cudaFuncSetAttribute(flash_bf16_kernel,
                             cudaFuncAttributeMaxDynamicSharedMemorySize, flash_smem);
        attr_set = 1;
    }

    // fp32 -> bf16 hi/lo splits of inputs
    {
        int n4;
        n4 = M_ * DIM_ / 4;
        split_kernel<<<n4 / 256, 256>>>((const float4*)x, (uint2*)xhi, (uint2*)xlo, n4);
        n4 = QD_ * DIM_ / 4;
        split_kernel<<<n4 / 256, 256>>>((const float4*)wq, (uint2*)wqhi, (uint2*)wqlo, n4);
        n4 = KD_ * DIM_ / 4;
        split_kernel<<<n4 / 256, 256>>>((const float4*)wk, (uint2*)wkhi, (uint2*)wklo, n4);
        split_kernel<<<n4 / 256, 256>>>((const float4*)wv, (uint2*)wvhi, (uint2*)wvlo, n4);
        n4 = DIM_ * QD_ / 4;
        split_kernel<<<n4 / 256, 256>>>((const float4*)wo, (uint2*)wohi, (uint2*)wolo, n4);
    }

    // QKV projections (RoPE fused for Q/K; outputs written pre-split)
    gemm_mma_bf16x3<<<dim3(QD_ / 128, M_ / 128), 256, GEMM_SMEM>>>(
        xhi, xlo, wqhi, wqlo, nullptr, qhi, qlo, QD_, DIM_, 1, freqs);
    gemm_mma_bf16x3<<<dim3(KD_ / 128, M_ / 128), 256, GEMM_SMEM>>>(
        xhi, xlo, wkhi, wklo, nullptr, khi, klo, KD_, DIM_, 1, freqs);
    gemm_mma_bf16x3<<<dim3(KD_ / 128, M_ / 128), 256, GEMM_SMEM>>>(
        xhi, xlo, wvhi, wvlo, nullptr, vhi, vlo, KD_, DIM_, 0, freqs);

    // Flash attention (split in, split out)
    flash_bf16_kernel<<<dim3(B_ * H_, S_ / 128), 256, flash_smem>>>(
        qhi, qlo, khi, klo, vhi, vlo, athi, atlo);

    // Output projection (fp32 out)
    gemm_mma_bf16x3<<<dim3(DIM_ / 128, M_ / 128), 256, GEMM_SMEM>>>(
        athi, atlo, wohi, wolo, out, nullptr, nullptr, DIM_, QD_, 0, freqs);
}

// round 11
// speedup vs baseline: 1.4317x; 1.4317x over previous
#include <cuda_runtime.h>
#include <math.h>
#include <float.h>

#define B_    2
#define S_    2048
#define DIM_  2048
#define H_    16
#define KVH_  4
#define HD_   128
#define G_    4
#define M_    (B_*S_)          // 4096 rows total
#define QD_   (H_*HD_)         // 2048
#define KD_   (KVH_*HD_)       // 512

// Scratch (device globals -- no allocation)
__device__ float g_q[(size_t)M_*QD_];     // [b,s,h,hd]
__device__ float g_k[(size_t)M_*KD_];     // [b,s,kvh,hd]
__device__ float g_v[(size_t)M_*KD_];
__device__ float g_attn[(size_t)M_*QD_];  // [b,s,h,hd]

// ---------------------------------------------------------------------------
// helpers
// ---------------------------------------------------------------------------
// pack two floats into bf16x2: low half = first arg, high half = second arg
__device__ __forceinline__ unsigned pk2(float lo_elem, float hi_elem) {
    unsigned d;
    asm("cvt.rn.bf16x2.f32 %0, %1, %2;" : "=r"(d) : "f"(hi_elem), "f"(lo_elem));
    return d;
}
__device__ __forceinline__ float blo(unsigned u) { return __uint_as_float(u << 16); }
__device__ __forceinline__ float bhi(unsigned u) { return __uint_as_float(u & 0xffff0000u); }

#define MMA_BF16(d, a0, a1, a2, a3, b0, b1) \
    asm volatile("mma.sync.aligned.m16n8k16.row.col.f32.bf16.bf16.f32 " \
                 "{%0,%1,%2,%3},{%4,%5,%6,%7},{%8,%9},{%0,%1,%2,%3};" \
                 : "+f"(d[0]), "+f"(d[1]), "+f"(d[2]), "+f"(d[3]) \
                 : "r"(a0), "r"(a1), "r"(a2), "r"(a3), "r"(b0), "r"(b1))

// ---------------------------------------------------------------------------
// bf16x3 tensor-core GEMM body (shared by generic and fused-QKV kernels):
// C[M,N] = A[M,K] * W[N,K]^T (fp32-accurate).
// 128x128x32 block tile, 256 threads (8 warps 2x4), warp tile 64x32.
// Operands split hi/lo bf16 ONCE at smem-fill; D += Ah*Bh + Ah*Bl + Al*Bh.
// Register-prefetch double buffer. Optional fused RoPE on the output pairs.
// smem words (u32 = bf16x2), row stride 20 (16 data + 4 pad):
//   per stage: AHI[128][20] ALO BHI BLO  = 10240 words; 2 stages = 80KB.
// ---------------------------------------------------------------------------
#define RS_   20
#define STG_  10240
#define AHI_O 0
#define ALO_O 2560
#define BHI_O 5120
#define BLO_O 7680

__device__ __forceinline__ void gemm_bf16x3_body(
    unsigned* smw,
    const float* __restrict__ A, const float* __restrict__ W,
    float* __restrict__ C, int Nn, int Kn, int m0, int n0,
    int do_rope, const float* __restrict__ freqs)
{
    const int tid  = threadIdx.x;
    const int lane = tid & 31;
    const int warp = tid >> 5;
    const int warpM = (warp >> 2) * 64;   // 0 or 64
    const int warpN = (warp & 3) * 32;    // 0,32,64,96
    const int r = lane >> 2;              // 0..7
    const int c = lane & 3;               // 0..3

    const int lrow = tid >> 3;            // 0..31
    const int lg   = tid & 7;             // k float4 group

    float acc[4][4][4];
#pragma unroll
    for (int i = 0; i < 4; ++i)
#pragma unroll
        for (int j = 0; j < 4; ++j)
#pragma unroll
            for (int t = 0; t < 4; ++t) acc[i][j][t] = 0.f;

    const int NT = Kn >> 5;

    float4 pa[4], pb[4];

    auto issue_loads = [&](int it) {
        size_t k0 = (size_t)it * 32 + lg * 4;
#pragma unroll
        for (int i = 0; i < 4; ++i) {
            int rr = lrow + i * 32;
            pa[i] = *(const float4*)&A[(size_t)(m0 + rr) * Kn + k0];
            pb[i] = *(const float4*)&W[(size_t)(n0 + rr) * Kn + k0];
        }
    };

    auto store_tile = [&](int p) {
        unsigned* base = smw + p * STG_;
#pragma unroll
        for (int i = 0; i < 4; ++i) {
            int rr = lrow + i * 32;
            int w = rr * RS_ + lg * 2;
            unsigned h0 = pk2(pa[i].x, pa[i].y), h1 = pk2(pa[i].z, pa[i].w);
            *(uint2*)&base[AHI_O + w] = make_uint2(h0, h1);
            *(uint2*)&base[ALO_O + w] = make_uint2(
                pk2(pa[i].x - blo(h0), pa[i].y - bhi(h0)),
                pk2(pa[i].z - blo(h1), pa[i].w - bhi(h1)));
            unsigned g0 = pk2(pb[i].x, pb[i].y), g1 = pk2(pb[i].z, pb[i].w);
            *(uint2*)&base[BHI_O + w] = make_uint2(g0, g1);
            *(uint2*)&base[BLO_O + w] = make_uint2(
                pk2(pb[i].x - blo(g0), pb[i].y - bhi(g0)),
                pk2(pb[i].z - blo(g1), pb[i].w - bhi(g1)));
        }
    };

    issue_loads(0);
    store_tile(0);
    __syncthreads();

    for (int it = 0; it < NT; ++it) {
        if (it + 1 < NT) issue_loads(it + 1);

        const unsigned* st = smw + (it & 1) * STG_;
#pragma unroll
        for (int kk = 0; kk < 2; ++kk) {
            unsigned bh_[4][2], bl_[4][2];
#pragma unroll
            for (int bn = 0; bn < 4; ++bn) {
                int bw = (warpN + bn * 8 + r) * RS_ + kk * 8 + c;
                bh_[bn][0] = st[BHI_O + bw]; bh_[bn][1] = st[BHI_O + bw + 4];
                bl_[bn][0] = st[BLO_O + bw]; bl_[bn][1] = st[BLO_O + bw + 4];
            }
#pragma unroll
            for (int am = 0; am < 4; ++am) {
                int aw = (warpM + am * 16 + r) * RS_ + kk * 8 + c;
                unsigned ah0 = st[AHI_O + aw];
                unsigned ah1 = st[AHI_O + aw + 8 * RS_];
                unsigned ah2 = st[AHI_O + aw + 4];
                unsigned ah3 = st[AHI_O + aw + 8 * RS_ + 4];
                unsigned al0 = st[ALO_O + aw];
                unsigned al1 = st[ALO_O + aw + 8 * RS_];
                unsigned al2 = st[ALO_O + aw + 4];
                unsigned al3 = st[ALO_O + aw + 8 * RS_ + 4];
#pragma unroll
                for (int bn = 0; bn < 4; ++bn) {
                    MMA_BF16(acc[am][bn], ah0, ah1, ah2, ah3, bh_[bn][0], bh_[bn][1]);
                    MMA_BF16(acc[am][bn], ah0, ah1, ah2, ah3, bl_[bn][0], bl_[bn][1]);
                    MMA_BF16(acc[am][bn], al0, al1, al2, al3, bh_[bn][0], bh_[bn][1]);
                }
            }
        }

        if (it + 1 < NT) store_tile((it + 1) & 1);
        __syncthreads();
    }

    // epilogue (optionally fused RoPE: output pair (n1, n1+1) is a rope pair)
#pragma unroll
    for (int am = 0; am < 4; ++am) {
        int m1 = m0 + warpM + am * 16 + r;
#pragma unroll
        for (int bn = 0; bn < 4; ++bn) {
            int n1 = n0 + warpN + bn * 8 + 2 * c;
            float2 v0 = make_float2(acc[am][bn][0], acc[am][bn][1]);
            float2 v1 = make_float2(acc[am][bn][2], acc[am][bn][3]);
            if (do_rope) {
                int j = (n1 & (HD_ - 1)) >> 1;
                int s0 = m1 & (S_ - 1);
                int s1 = (m1 + 8) & (S_ - 1);
                float2 cs0 = *(const float2*)&freqs[((size_t)s0 * 64 + j) * 2];
                float2 cs1 = *(const float2*)&freqs[((size_t)s1 * 64 + j) * 2];
                v0 = make_float2(v0.x * cs0.x - v0.y * cs0.y,
                                 v0.x * cs0.y + v0.y * cs0.x);
                v1 = make_float2(v1.x * cs1.x - v1.y * cs1.y,
                                 v1.x * cs1.y + v1.y * cs1.x);
            }
            *(float2*)&C[(size_t)m1 * Nn + n1] = v0;
            *(float2*)&C[(size_t)(m1 + 8) * Nn + n1] = v1;
        }
    }
}

// Generic GEMM (used for the output projection)
__global__ __launch_bounds__(256, 2) void gemm_bf16x3_kernel(
    const float* __restrict__ A, const float* __restrict__ W,
    float* __restrict__ C, int Nn, int Kn,
    int do_rope, const float* __restrict__ freqs)
{
    extern __shared__ unsigned smw[];
    gemm_bf16x3_body(smw, A, W, C, Nn, Kn,
                     blockIdx.y * 128, blockIdx.x * 128, do_rope, freqs);
}

// Fused QKV GEMM: one launch covers wq (16 n-tiles), wk (4), wv (4).
// blockIdx.x in [0,24): routes to the right weight/output/rope flag.
// Eliminates the half-empty waves of the separate K/V launches.
__global__ __launch_bounds__(256, 2) void gemm_qkv_fused_kernel(
    const float* __restrict__ X,
    const float* __restrict__ WQ, const float* __restrict__ WK,
    const float* __restrict__ WV,
    float* __restrict__ Qo, float* __restrict__ Ko, float* __restrict__ Vo,
    const float* __restrict__ freqs)
{
    extern __shared__ unsigned smw[];
    const int bx = blockIdx.x;
    const float* W;
    float* C;
    int Nn, n0, rope;
    if (bx < 16)      { W = WQ; C = Qo; Nn = QD_; n0 = bx * 128;        rope = 1; }
    else if (bx < 20) { W = WK; C = Ko; Nn = KD_; n0 = (bx - 16) * 128; rope = 1; }
    else              { W = WV; C = Vo; Nn = KD_; n0 = (bx - 20) * 128; rope = 0; }
    gemm_bf16x3_body(smw, X, W, C, Nn, DIM_, blockIdx.y * 128, n0, rope, freqs);
}

// ---------------------------------------------------------------------------
// Flash attention, bf16x3 tensor-core version (causal, GQA).
// Block: 256 thr (8 warps). q-tile 128 rows, kv-tile 64. Warp w owns q rows
// [w*16, w*16+16). Q/K/V split hi/lo bf16 in smem; P kept in registers.
// ---------------------------------------------------------------------------
#define QHI_OFF 0
#define QLO_OFF 8704
#define KHI_OFF 17408
#define KLO_OFF 21760
#define VHI_OFF 26112
#define VLO_OFF 30464
#define FLASH_SMEM_WORDS 34816

__global__ __launch_bounds__(256, 1) void flash_bf16_kernel(
    const float* __restrict__ Q, const float* __restrict__ K,
    const float* __restrict__ V, float* __restrict__ O)
{
    extern __shared__ unsigned smw[];
    unsigned* QHI = smw + QHI_OFF;
    unsigned* QLO = smw + QLO_OFF;
    unsigned* KHI = smw + KHI_OFF;
    unsigned* KLO = smw + KLO_OFF;
    unsigned* VHI = smw + VHI_OFF;
    unsigned* VLO = smw + VLO_OFF;
    const unsigned smb = (unsigned)__cvta_generic_to_shared(smw);

    const int bh = blockIdx.x;                 // 0..31
    const int ib = (int)gridDim.y - 1 - (int)blockIdx.y;  // heavy tiles first
    const int b  = bh / H_;
    const int h  = bh % H_;
    const int kv = h / G_;

    const float* Qg = Q + (size_t)b * S_ * QD_ + (size_t)h * HD_;
    const float* Kg = K + (size_t)b * S_ * KD_ + (size_t)kv * HD_;
    const float* Vg = V + (size_t)b * S_ * KD_ + (size_t)kv * HD_;

    const int tid  = threadIdx.x;
    const int lane = tid & 31;
    const int warp = tid >> 5;
    const int r = lane >> 2;      // 0..7
    const int c = lane & 3;       // 0..3
    const float scale = 0.08838834764831845f;

    // ---- load + convert Q tile (128 x 128) once ----
    for (int i = tid; i < 128 * 32; i += 256) {
        int row = i >> 5;
        int hd4 = (i & 31) * 4;
        float4 f = *(const float4*)&Qg[(size_t)(ib * 128 + row) * QD_ + hd4];
        unsigned h0 = pk2(f.x, f.y), h1 = pk2(f.z, f.w);
        unsigned l0 = pk2(f.x - blo(h0), f.y - bhi(h0));
        unsigned l1 = pk2(f.z - blo(h1), f.w - bhi(h1));
        int w = row * 68 + (hd4 >> 1);
        QHI[w] = h0; QHI[w + 1] = h1;
        QLO[w] = l0; QLO[w + 1] = l1;
    }

    float m0 = -1e30f, m1 = -1e30f, l0s = 0.f, l1s = 0.f;
    float acc[16][4];
#pragma unroll
    for (int t = 0; t < 16; ++t)
#pragma unroll
        for (int e = 0; e < 4; ++e) acc[t][e] = 0.f;

    const int qr0 = ib * 128 + warp * 16 + r;
    const int qr1 = qr0 + 8;
    const int jmax = 2 * ib + 1;

    for (int j = 0; j <= jmax; ++j) {
        __syncthreads();
        // ---- load + convert K and V tiles (64 x 128 each) ----
        for (int i = tid; i < 64 * 32; i += 256) {
            int row = i >> 5;
            int hd4 = (i & 31) * 4;
            int w = row * 68 + (hd4 >> 1);
            float4 f = *(const float4*)&Kg[(size_t)(j * 64 + row) * KD_ + hd4];
            unsigned h0 = pk2(f.x, f.y), h1 = pk2(f.z, f.w);
            KHI[w] = h0; KHI[w + 1] = h1;
            KLO[w]     = pk2(f.x - blo(h0), f.y - bhi(h0));
            KLO[w + 1] = pk2(f.z - blo(h1), f.w - bhi(h1));
            float4 g = *(const float4*)&Vg[(size_t)(j * 64 + row) * KD_ + hd4];
            unsigned v0 = pk2(g.x, g.y), v1 = pk2(g.z, g.w);
            VHI[w] = v0; VHI[w + 1] = v1;
            VLO[w]     = pk2(g.x - blo(v0), g.y - bhi(v0));
            VLO[w + 1] = pk2(g.z - blo(v1), g.w - bhi(v1));
        }
        __syncthreads();

        // ---- QK^T ----
        float s[8][4];
#pragma unroll
        for (int bn = 0; bn < 8; ++bn)
#pragma unroll
            for (int e = 0; e < 4; ++e) s[bn][e] = 0.f;

#pragma unroll
        for (int kk = 0; kk < 8; ++kk) {
            int a0i = (warp * 16 + r) * 68 + kk * 8 + c;
            int a1i = a0i + 8 * 68;
            unsigned ah0 = QHI[a0i], ah1 = QHI[a1i], ah2 = QHI[a0i + 4], ah3 = QHI[a1i + 4];
            unsigned al0 = QLO[a0i], al1 = QLO[a1i], al2 = QLO[a0i + 4], al3 = QLO[a1i + 4];
#pragma unroll
            for (int bn = 0; bn < 8; ++bn) {
                int bi = (bn * 8 + r) * 68 + kk * 8 + c;
                unsigned kb0 = KHI[bi], kb1 = KHI[bi + 4];
                unsigned kl0 = KLO[bi], kl1 = KLO[bi + 4];
                MMA_BF16(s[bn], ah0, ah1, ah2, ah3, kb0, kb1);
                MMA_BF16(s[bn], ah0, ah1, ah2, ah3, kl0, kl1);
                MMA_BF16(s[bn], al0, al1, al2, al3, kb0, kb1);
            }
        }

        // ---- scale, mask, online softmax ----
        const bool need_mask = (j >= 2 * ib);
        float vmax0 = -1e30f, vmax1 = -1e30f;
#pragma unroll
        for (int bn = 0; bn < 8; ++bn) {
#pragma unroll
            for (int e = 0; e < 2; ++e) {
                int col = j * 64 + bn * 8 + 2 * c + e;
                float v0 = s[bn][e] * scale;
                if (need_mask && col > qr0) v0 = -1e30f;
                s[bn][e] = v0;
                vmax0 = fmaxf(vmax0, v0);
                float v1 = s[bn][2 + e] * scale;
                if (need_mask && col > qr1) v1 = -1e30f;
                s[bn][2 + e] = v1;
                vmax1 = fmaxf(vmax1, v1);
            }
        }
        vmax0 = fmaxf(vmax0, __shfl_xor_sync(0xffffffffu, vmax0, 1));
        vmax0 = fmaxf(vmax0, __shfl_xor_sync(0xffffffffu, vmax0, 2));
        vmax1 = fmaxf(vmax1, __shfl_xor_sync(0xffffffffu, vmax1, 1));
        vmax1 = fmaxf(vmax1, __shfl_xor_sync(0xffffffffu, vmax1, 2));

        float mn0 = fmaxf(m0, vmax0), mn1 = fmaxf(m1, vmax1);
        float alpha0 = __expf(m0 - mn0), alpha1 = __expf(m1 - mn1);
        m0 = mn0; m1 = mn1;

        float rs0 = 0.f, rs1 = 0.f;
#pragma unroll
        for (int bn = 0; bn < 8; ++bn) {
#pragma unroll
            for (int e = 0; e < 2; ++e) {
                float p0 = __expf(s[bn][e] - mn0);
                s[bn][e] = p0; rs0 += p0;
                float p1 = __expf(s[bn][2 + e] - mn1);
                s[bn][2 + e] = p1; rs1 += p1;
            }
        }
        rs0 += __shfl_xor_sync(0xffffffffu, rs0, 1);
        rs0 += __shfl_xor_sync(0xffffffffu, rs0, 2);
        rs1 += __shfl_xor_sync(0xffffffffu, rs1, 1);
        rs1 += __shfl_xor_sync(0xffffffffu, rs1, 2);
        l0s = l0s * alpha0 + rs0;
        l1s = l1s * alpha1 + rs1;

#pragma unroll
        for (int t = 0; t < 16; ++t) {
            acc[t][0] *= alpha0; acc[t][1] *= alpha0;
            acc[t][2] *= alpha1; acc[t][3] *= alpha1;
        }

        // ---- PV ----
#pragma unroll
        for (int kk = 0; kk < 4; ++kk) {
            unsigned ph0 = pk2(s[2 * kk][0], s[2 * kk][1]);
            unsigned ph1 = pk2(s[2 * kk][2], s[2 * kk][3]);
            unsigned ph2 = pk2(s[2 * kk + 1][0], s[2 * kk + 1][1]);
            unsigned ph3 = pk2(s[2 * kk + 1][2], s[2 * kk + 1][3]);
            unsigned pl0 = pk2(s[2 * kk][0] - blo(ph0), s[2 * kk][1] - bhi(ph0));
            unsigned pl1 = pk2(s[2 * kk][2] - blo(ph1), s[2 * kk][3] - bhi(ph1));
            unsigned pl2 = pk2(s[2 * kk + 1][0] - blo(ph2), s[2 * kk + 1][1] - bhi(ph2));
            unsigned pl3 = pk2(s[2 * kk + 1][2] - blo(ph3), s[2 * kk + 1][3] - bhi(ph3));

            int sel = lane >> 3;
            int lrw = lane & 7;
            int vrow = kk * 16 + (sel & 1) * 8 + lrw;
            int coff = (sel >> 1) * 8;

#pragma unroll
            for (int t = 0; t < 16; t += 2) {
                unsigned addr_h = smb + VHI_OFF * 4u + (unsigned)(vrow * 272 + (t * 8 + coff) * 2);
                unsigned addr_l = smb + VLO_OFF * 4u + (unsigned)(vrow * 272 + (t * 8 + coff) * 2);
                unsigned vh0, vh1, vh2, vh3, vl0, vl1, vl2, vl3;
                asm volatile("ldmatrix.sync.aligned.m8n8.x4.trans.shared.b16 {%0,%1,%2,%3}, [%4];"
                             : "=r"(vh0), "=r"(vh1), "=r"(vh2), "=r"(vh3) : "r"(addr_h));
                asm volatile("ldmatrix.sync.aligned.m8n8.x4.trans.shared.b16 {%0,%1,%2,%3}, [%4];"
                             : "=r"(vl0), "=r"(vl1), "=r"(vl2), "=r"(vl3) : "r"(addr_l));
                MMA_BF16(acc[t],     ph0, ph1, ph2, ph3, vh0, vh1);
                MMA_BF16(acc[t],     ph0, ph1, ph2, ph3, vl0, vl1);
                MMA_BF16(acc[t],     pl0, pl1, pl2, pl3, vh0, vh1);
                MMA_BF16(acc[t + 1], ph0, ph1, ph2, ph3, vh2, vh3);
                MMA_BF16(acc[t + 1], ph0, ph1, ph2, ph3, vl2, vl3);
                MMA_BF16(acc[t + 1], pl0, pl1, pl2, pl3, vh2, vh3);
            }
        }
    }

    // ---- epilogue ----
    float inv0 = 1.f / l0s, inv1 = 1.f / l1s;
#pragma unroll
    for (int t = 0; t < 16; ++t) {
        int col = t * 8 + 2 * c;
        float* d0 = O + (size_t)(b * S_ + qr0) * QD_ + (size_t)h * HD_ + col;
        float* d1 = O + (size_t)(b * S_ + qr1) * QD_ + (size_t)h * HD_ + col;
        *(float2*)d0 = make_float2(acc[t][0] * inv0, acc[t][1] * inv0);
        *(float2*)d1 = make_float2(acc[t][2] * inv1, acc[t][3] * inv1);
    }
}

// ---------------------------------------------------------------------------
extern "C" void kernel_launch(void* const* d_in, const int* in_sizes, int n_in,
                              void* d_out, int out_size)
{
    const float* x     = (const float*)d_in[0];
    const float* freqs = (const float*)d_in[1];
    const float* wq    = (const float*)d_in[2];
    const float* wk    = (const float*)d_in[3];
    const float* wv    = (const float*)d_in[4];
    const float* wo    = (const float*)d_in[5];
    float* out = (float*)d_out;

    float *q, *k, *v, *attn;
    cudaGetSymbolAddress((void**)&q,    g_q);
    cudaGetSymbolAddress((void**)&k,    g_k);
    cudaGetSymbolAddress((void**)&v,    g_v);
    cudaGetSymbolAddress((void**)&attn, g_attn);

    static int attr_set = 0;
    const int gemm_smem  = 2 * STG_ * 4;          // 81920
    const int flash_smem = FLASH_SMEM_WORDS * 4;  // 139264
    if (!attr_set) {
        cudaFuncSetAttribute(gemm_bf16x3_kernel,
                             cudaFuncAttributeMaxDynamicSharedMemorySize, gemm_smem);
        cudaFuncSetAttribute(gemm_qkv_fused_kernel,
                             cudaFuncAttributeMaxDynamicSharedMemorySize, gemm_smem);
        cudaFuncSetAttribute(flash_bf16_kernel,
                             cudaFuncAttributeMaxDynamicSharedMemorySize, flash_smem);
        attr_set = 1;
    }

    // Fused QKV projection: one 768-block launch (16 Q + 4 K + 4 V n-tiles)
    gemm_qkv_fused_kernel<<<dim3(24, M_ / 128), 256, gemm_smem>>>(
        x, wq, wk, wv, q, k, v, freqs);

    // Flash attention (bf16x3 tensor-core)
    flash_bf16_kernel<<<dim3(B_ * H_, S_ / 128), 256, flash_smem>>>(q, k, v, attn);

    // Output projection (bf16x3 tensor-core)
    gemm_bf16x3_kernel<<<dim3(DIM_ / 128, M_ / 128), 256, gemm_smem>>>(
        attn, wo, out, DIM_, QD_, 0, freqs);
}

// round 12
// speedup vs baseline: 1.5286x; 1.0677x over previous
#include <cuda_runtime.h>
#include <math.h>
#include <float.h>

#define B_    2
#define S_    2048
#define DIM_  2048
#define H_    16
#define KVH_  4
#define HD_   128
#define G_    4
#define M_    (B_*S_)          // 4096 rows total
#define QD_   (H_*HD_)         // 2048
#define KD_   (KVH_*HD_)       // 512

// Scratch (device globals -- no allocation)
__device__ float g_q[(size_t)M_*QD_];     // [b,s,h,hd]
__device__ float g_k[(size_t)M_*KD_];     // [b,s,kvh,hd]
__device__ float g_v[(size_t)M_*KD_];
__device__ float g_attn[(size_t)M_*QD_];  // [b,s,h,hd]

// ---------------------------------------------------------------------------
// helpers
// ---------------------------------------------------------------------------
// pack two floats into bf16x2: low half = first arg, high half = second arg
__device__ __forceinline__ unsigned pk2(float lo_elem, float hi_elem) {
    unsigned d;
    asm("cvt.rn.bf16x2.f32 %0, %1, %2;" : "=r"(d) : "f"(hi_elem), "f"(lo_elem));
    return d;
}
__device__ __forceinline__ float blo(unsigned u) { return __uint_as_float(u << 16); }
__device__ __forceinline__ float bhi(unsigned u) { return __uint_as_float(u & 0xffff0000u); }

#define MMA_BF16(d, a0, a1, a2, a3, b0, b1) \
    asm volatile("mma.sync.aligned.m16n8k16.row.col.f32.bf16.bf16.f32 " \
                 "{%0,%1,%2,%3},{%4,%5,%6,%7},{%8,%9},{%0,%1,%2,%3};" \
                 : "+f"(d[0]), "+f"(d[1]), "+f"(d[2]), "+f"(d[3]) \
                 : "r"(a0), "r"(a1), "r"(a2), "r"(a3), "r"(b0), "r"(b1))

#define LDSM4(r0, r1, r2, r3, addr) \
    asm volatile("ldmatrix.sync.aligned.m8n8.x4.shared.b16 {%0,%1,%2,%3}, [%4];" \
                 : "=r"(r0), "=r"(r1), "=r"(r2), "=r"(r3) : "r"(addr))

// ---------------------------------------------------------------------------
// bf16x3 tensor-core GEMM body: C[M,N] = A[M,K] * W[N,K]^T (fp32-accurate).
// 128x128x32 block tile, 256 threads (8 warps 2x4), warp tile 64x32.
// Operands split hi/lo bf16 ONCE at smem-fill; D += Ah*Bh + Ah*Bl + Al*Bh.
// Register-prefetch double buffer; ldmatrix.x4 fragment loads.
// smem words (u32 = bf16x2), row stride 20 (16 data + 4 pad):
//   per stage: AHI[128][20] ALO BHI BLO  = 10240 words; 2 stages = 80KB.
// ldmatrix bank check: rows at 20-word spacing -> 20r mod 32 =
// {0,20,8,28,16,4,24,12}, each a distinct 4-bank 16B chunk => all 32 banks.
// ---------------------------------------------------------------------------
#define RS_   20
#define STG_  10240
#define AHI_O 0
#define ALO_O 2560
#define BHI_O 5120
#define BLO_O 7680

__device__ __forceinline__ void gemm_bf16x3_body(
    unsigned* smw,
    const float* __restrict__ A, const float* __restrict__ W,
    float* __restrict__ C, int Nn, int Kn, int m0, int n0,
    int do_rope, const float* __restrict__ freqs)
{
    const unsigned smb = (unsigned)__cvta_generic_to_shared(smw);
    const int tid  = threadIdx.x;
    const int lane = tid & 31;
    const int warp = tid >> 5;
    const int warpM = (warp >> 2) * 64;   // 0 or 64
    const int warpN = (warp & 3) * 32;    // 0,32,64,96
    const int r = lane >> 2;              // 0..7
    const int c = lane & 3;               // 0..3
    const int grp = lane >> 3;            // ldmatrix matrix selector
    const int lr  = lane & 7;             // row within 8

    const int lrow = tid >> 3;            // 0..31
    const int lg   = tid & 7;             // k float4 group

    float acc[4][4][4];
#pragma unroll
    for (int i = 0; i < 4; ++i)
#pragma unroll
        for (int j = 0; j < 4; ++j)
#pragma unroll
            for (int t = 0; t < 4; ++t) acc[i][j][t] = 0.f;

    const int NT = Kn >> 5;

    float4 pa[4], pb[4];

    auto issue_loads = [&](int it) {
        size_t k0 = (size_t)it * 32 + lg * 4;
#pragma unroll
        for (int i = 0; i < 4; ++i) {
            int rr = lrow + i * 32;
            pa[i] = *(const float4*)&A[(size_t)(m0 + rr) * Kn + k0];
            pb[i] = *(const float4*)&W[(size_t)(n0 + rr) * Kn + k0];
        }
    };

    auto store_tile = [&](int p) {
        unsigned* base = smw + p * STG_;
#pragma unroll
        for (int i = 0; i < 4; ++i) {
            int rr = lrow + i * 32;
            int w = rr * RS_ + lg * 2;
            unsigned h0 = pk2(pa[i].x, pa[i].y), h1 = pk2(pa[i].z, pa[i].w);
            *(uint2*)&base[AHI_O + w] = make_uint2(h0, h1);
            *(uint2*)&base[ALO_O + w] = make_uint2(
                pk2(pa[i].x - blo(h0), pa[i].y - bhi(h0)),
                pk2(pa[i].z - blo(h1), pa[i].w - bhi(h1)));
            unsigned g0 = pk2(pb[i].x, pb[i].y), g1 = pk2(pb[i].z, pb[i].w);
            *(uint2*)&base[BHI_O + w] = make_uint2(g0, g1);
            *(uint2*)&base[BLO_O + w] = make_uint2(
                pk2(pb[i].x - blo(g0), pb[i].y - bhi(g0)),
                pk2(pb[i].z - blo(g1), pb[i].w - bhi(g1)));
        }
    };

    issue_loads(0);
    store_tile(0);
    __syncthreads();

    for (int it = 0; it < NT; ++it) {
        if (it + 1 < NT) issue_loads(it + 1);

        const unsigned sbase = smb + (unsigned)((it & 1) * STG_ * 4);
#pragma unroll
        for (int kk = 0; kk < 2; ++kk) {
            // B fragments via ldmatrix: 2 bp groups x (hi, lo)
            // matrix order: m0=(rows+0..7,k0) m1=(rows0..7,k1) m2=(+8..15,k0) m3=(+8..15,k1)
            unsigned bh_[2][4], bl_[2][4];
#pragma unroll
            for (int bp = 0; bp < 2; ++bp) {
                unsigned baddr = sbase + BHI_O * 4u +
                    (unsigned)(((warpN + bp * 16 + (grp >> 1) * 8 + lr) * RS_ + kk * 8) * 4 + (grp & 1) * 16);
                LDSM4(bh_[bp][0], bh_[bp][1], bh_[bp][2], bh_[bp][3], baddr);
                LDSM4(bl_[bp][0], bl_[bp][1], bl_[bp][2], bl_[bp][3], baddr + 10240u);
            }
#pragma unroll
            for (int am = 0; am < 4; ++am) {
                // A fragments: m0=(rows0..7,k0) m1=(+8,k0) m2=(rows0..7,k1) m3=(+8,k1)
                unsigned aaddr = sbase +
                    (unsigned)(((warpM + am * 16 + (grp & 1) * 8 + lr) * RS_ + kk * 8) * 4 + (grp >> 1) * 16);
                unsigned ah0, ah1, ah2, ah3, al0, al1, al2, al3;
                LDSM4(ah0, ah1, ah2, ah3, aaddr);
                LDSM4(al0, al1, al2, al3, aaddr + 10240u);
#pragma unroll
                for (int bn = 0; bn < 4; ++bn) {
                    const int bp = bn >> 1, off = (bn & 1) * 2;
                    MMA_BF16(acc[am][bn], ah0, ah1, ah2, ah3, bh_[bp][off], bh_[bp][off + 1]);
                    MMA_BF16(acc[am][bn], ah0, ah1, ah2, ah3, bl_[bp][off], bl_[bp][off + 1]);
                    MMA_BF16(acc[am][bn], al0, al1, al2, al3, bh_[bp][off], bh_[bp][off + 1]);
                }
            }
        }

        if (it + 1 < NT) store_tile((it + 1) & 1);
        __syncthreads();
    }

    // epilogue (optionally fused RoPE: output pair (n1, n1+1) is a rope pair)
#pragma unroll
    for (int am = 0; am < 4; ++am) {
        int m1 = m0 + warpM + am * 16 + r;
#pragma unroll
        for (int bn = 0; bn < 4; ++bn) {
            int n1 = n0 + warpN + bn * 8 + 2 * c;
            float2 v0 = make_float2(acc[am][bn][0], acc[am][bn][1]);
            float2 v1 = make_float2(acc[am][bn][2], acc[am][bn][3]);
            if (do_rope) {
                int j = (n1 & (HD_ - 1)) >> 1;
                int s0 = m1 & (S_ - 1);
                int s1 = (m1 + 8) & (S_ - 1);
                float2 cs0 = *(const float2*)&freqs[((size_t)s0 * 64 + j) * 2];
                float2 cs1 = *(const float2*)&freqs[((size_t)s1 * 64 + j) * 2];
                v0 = make_float2(v0.x * cs0.x - v0.y * cs0.y,
                                 v0.x * cs0.y + v0.y * cs0.x);
                v1 = make_float2(v1.x * cs1.x - v1.y * cs1.y,
                                 v1.x * cs1.y + v1.y * cs1.x);
            }
            *(float2*)&C[(size_t)m1 * Nn + n1] = v0;
            *(float2*)&C[(size_t)(m1 + 8) * Nn + n1] = v1;
        }
    }
}

// Generic GEMM (used for the output projection)
__global__ __launch_bounds__(256, 2) void gemm_bf16x3_kernel(
    const float* __restrict__ A, const float* __restrict__ W,
    float* __restrict__ C, int Nn, int Kn,
    int do_rope, const float* __restrict__ freqs)
{
    extern __shared__ unsigned smw[];
    gemm_bf16x3_body(smw, A, W, C, Nn, Kn,
                     blockIdx.y * 128, blockIdx.x * 128, do_rope, freqs);
}

// Fused QKV GEMM: one launch covers wq (16 n-tiles), wk (4), wv (4).
__global__ __launch_bounds__(256, 2) void gemm_qkv_fused_kernel(
    const float* __restrict__ X,
    const float* __restrict__ WQ, const float* __restrict__ WK,
    const float* __restrict__ WV,
    float* __restrict__ Qo, float* __restrict__ Ko, float* __restrict__ Vo,
    const float* __restrict__ freqs)
{
    extern __shared__ unsigned smw[];
    const int bx = blockIdx.x;
    const float* W;
    float* C;
    int Nn, n0, rope;
    if (bx < 16)      { W = WQ; C = Qo; Nn = QD_; n0 = bx * 128;        rope = 1; }
    else if (bx < 20) { W = WK; C = Ko; Nn = KD_; n0 = (bx - 16) * 128; rope = 1; }
    else              { W = WV; C = Vo; Nn = KD_; n0 = (bx - 20) * 128; rope = 0; }
    gemm_bf16x3_body(smw, X, W, C, Nn, DIM_, blockIdx.y * 128, n0, rope, freqs);
}

// ---------------------------------------------------------------------------
// Flash attention, bf16x3 tensor-core version (causal, GQA).
// Block: 256 thr (8 warps). q-tile 128 rows, kv-tile 64. Warp w owns q rows
// [w*16, w*16+16). Q/K/V split hi/lo bf16 in smem; P kept in registers.
// QK^T fragment loads via ldmatrix (68-word stride: 68 mod 32 = 4 ->
// rows hit {0,4,...,28} 4-bank chunks = all 32 banks, conflict-free).
// ---------------------------------------------------------------------------
#define QHI_OFF 0
#define QLO_OFF 8704
#define KHI_OFF 17408
#define KLO_OFF 21760
#define VHI_OFF 26112
#define VLO_OFF 30464
#define FLASH_SMEM_WORDS 34816

__global__ __launch_bounds__(256, 1) void flash_bf16_kernel(
    const float* __restrict__ Q, const float* __restrict__ K,
    const float* __restrict__ V, float* __restrict__ O)
{
    extern __shared__ unsigned smw[];
    unsigned* QHI = smw + QHI_OFF;
    unsigned* QLO = smw + QLO_OFF;
    unsigned* KHI = smw + KHI_OFF;
    unsigned* KLO = smw + KLO_OFF;
    unsigned* VHI = smw + VHI_OFF;
    unsigned* VLO = smw + VLO_OFF;
    const unsigned smb = (unsigned)__cvta_generic_to_shared(smw);

    const int bh = blockIdx.x;                 // 0..31
    const int ib = (int)gridDim.y - 1 - (int)blockIdx.y;  // heavy tiles first
    const int b  = bh / H_;
    const int h  = bh % H_;
    const int kv = h / G_;

    const float* Qg = Q + (size_t)b * S_ * QD_ + (size_t)h * HD_;
    const float* Kg = K + (size_t)b * S_ * KD_ + (size_t)kv * HD_;
    const float* Vg = V + (size_t)b * S_ * KD_ + (size_t)kv * HD_;

    const int tid  = threadIdx.x;
    const int lane = tid & 31;
    const int warp = tid >> 5;
    const int r = lane >> 2;      // 0..7
    const int c = lane & 3;       // 0..3
    const int grp = lane >> 3;    // ldmatrix selector
    const int lr  = lane & 7;
    const float scale = 0.08838834764831845f;

    // ---- load + convert Q tile (128 x 128) once ----
    for (int i = tid; i < 128 * 32; i += 256) {
        int row = i >> 5;
        int hd4 = (i & 31) * 4;
        float4 f = *(const float4*)&Qg[(size_t)(ib * 128 + row) * QD_ + hd4];
        unsigned h0 = pk2(f.x, f.y), h1 = pk2(f.z, f.w);
        unsigned l0 = pk2(f.x - blo(h0), f.y - bhi(h0));
        unsigned l1 = pk2(f.z - blo(h1), f.w - bhi(h1));
        int w = row * 68 + (hd4 >> 1);
        QHI[w] = h0; QHI[w + 1] = h1;
        QLO[w] = l0; QLO[w + 1] = l1;
    }

    float m0 = -1e30f, m1 = -1e30f, l0s = 0.f, l1s = 0.f;
    float acc[16][4];
#pragma unroll
    for (int t = 0; t < 16; ++t)
#pragma unroll
        for (int e = 0; e < 4; ++e) acc[t][e] = 0.f;

    const int qr0 = ib * 128 + warp * 16 + r;
    const int qr1 = qr0 + 8;
    const int jmax = 2 * ib + 1;

    for (int j = 0; j <= jmax; ++j) {
        __syncthreads();
        // ---- load + convert K and V tiles (64 x 128 each) ----
        for (int i = tid; i < 64 * 32; i += 256) {
            int row = i >> 5;
            int hd4 = (i & 31) * 4;
            int w = row * 68 + (hd4 >> 1);
            float4 f = *(const float4*)&Kg[(size_t)(j * 64 + row) * KD_ + hd4];
            unsigned h0 = pk2(f.x, f.y), h1 = pk2(f.z, f.w);
            KHI[w] = h0; KHI[w + 1] = h1;
            KLO[w]     = pk2(f.x - blo(h0), f.y - bhi(h0));
            KLO[w + 1] = pk2(f.z - blo(h1), f.w - bhi(h1));
            float4 g = *(const float4*)&Vg[(size_t)(j * 64 + row) * KD_ + hd4];
            unsigned v0 = pk2(g.x, g.y), v1 = pk2(g.z, g.w);
            VHI[w] = v0; VHI[w + 1] = v1;
            VLO[w]     = pk2(g.x - blo(v0), g.y - bhi(v0));
            VLO[w + 1] = pk2(g.z - blo(v1), g.w - bhi(v1));
        }
        __syncthreads();

        // ---- QK^T (ldmatrix fragments) ----
        float s[8][4];
#pragma unroll
        for (int bn = 0; bn < 8; ++bn)
#pragma unroll
            for (int e = 0; e < 4; ++e) s[bn][e] = 0.f;

#pragma unroll
        for (int kk = 0; kk < 8; ++kk) {
            unsigned qaddr = smb +
                (unsigned)(((warp * 16 + (grp & 1) * 8 + lr) * 68 + kk * 8) * 4 + (grp >> 1) * 16);
            unsigned ah0, ah1, ah2, ah3, al0, al1, al2, al3;
            LDSM4(ah0, ah1, ah2, ah3, qaddr);
            LDSM4(al0, al1, al2, al3, qaddr + QLO_OFF * 4u);
#pragma unroll
            for (int bp = 0; bp < 4; ++bp) {
                unsigned kaddr = smb + KHI_OFF * 4u +
                    (unsigned)(((bp * 16 + (grp >> 1) * 8 + lr) * 68 + kk * 8) * 4 + (grp & 1) * 16);
                unsigned kh[4], kl[4];
                LDSM4(kh[0], kh[1], kh[2], kh[3], kaddr);
                LDSM4(kl[0], kl[1], kl[2], kl[3], kaddr + (KLO_OFF - KHI_OFF) * 4u);
                MMA_BF16(s[2 * bp],     ah0, ah1, ah2, ah3, kh[0], kh[1]);
                MMA_BF16(s[2 * bp],     ah0, ah1, ah2, ah3, kl[0], kl[1]);
                MMA_BF16(s[2 * bp],     al0, al1, al2, al3, kh[0], kh[1]);
                MMA_BF16(s[2 * bp + 1], ah0, ah1, ah2, ah3, kh[2], kh[3]);
                MMA_BF16(s[2 * bp + 1], ah0, ah1, ah2, ah3, kl[2], kl[3]);
                MMA_BF16(s[2 * bp + 1], al0, al1, al2, al3, kh[2], kh[3]);
            }
        }

        // ---- scale, mask, online softmax ----
        const bool need_mask = (j >= 2 * ib);
        float vmax0 = -1e30f, vmax1 = -1e30f;
#pragma unroll
        for (int bn = 0; bn < 8; ++bn) {
#pragma unroll
            for (int e = 0; e < 2; ++e) {
                int col = j * 64 + bn * 8 + 2 * c + e;
                float v0 = s[bn][e] * scale;
                if (need_mask && col > qr0) v0 = -1e30f;
                s[bn][e] = v0;
                vmax0 = fmaxf(vmax0, v0);
                float v1 = s[bn][2 + e] * scale;
                if (need_mask && col > qr1) v1 = -1e30f;
                s[bn][2 + e] = v1;
                vmax1 = fmaxf(vmax1, v1);
            }
        }
        vmax0 = fmaxf(vmax0, __shfl_xor_sync(0xffffffffu, vmax0, 1));
        vmax0 = fmaxf(vmax0, __shfl_xor_sync(0xffffffffu, vmax0, 2));
        vmax1 = fmaxf(vmax1, __shfl_xor_sync(0xffffffffu, vmax1, 1));
        vmax1 = fmaxf(vmax1, __shfl_xor_sync(0xffffffffu, vmax1, 2));

        float mn0 = fmaxf(m0, vmax0), mn1 = fmaxf(m1, vmax1);
        float alpha0 = __expf(m0 - mn0), alpha1 = __expf(m1 - mn1);
        m0 = mn0; m1 = mn1;

        float rs0 = 0.f, rs1 = 0.f;
#pragma unroll
        for (int bn = 0; bn < 8; ++bn) {
#pragma unroll
            for (int e = 0; e < 2; ++e) {
                float p0 = __expf(s[bn][e] - mn0);
                s[bn][e] = p0; rs0 += p0;
                float p1 = __expf(s[bn][2 + e] - mn1);
                s[bn][2 + e] = p1; rs1 += p1;
            }
        }
        rs0 += __shfl_xor_sync(0xffffffffu, rs0, 1);
        rs0 += __shfl_xor_sync(0xffffffffu, rs0, 2);
        rs1 += __shfl_xor_sync(0xffffffffu, rs1, 1);
        rs1 += __shfl_xor_sync(0xffffffffu, rs1, 2);
        l0s = l0s * alpha0 + rs0;
        l1s = l1s * alpha1 + rs1;

#pragma unroll
        for (int t = 0; t < 16; ++t) {
            acc[t][0] *= alpha0; acc[t][1] *= alpha0;
            acc[t][2] *= alpha1; acc[t][3] *= alpha1;
        }

        // ---- PV ----
#pragma unroll
        for (int kk = 0; kk < 4; ++kk) {
            unsigned ph0 = pk2(s[2 * kk][0], s[2 * kk][1]);
            unsigned ph1 = pk2(s[2 * kk][2], s[2 * kk][3]);
            unsigned ph2 = pk2(s[2 * kk + 1][0], s[2 * kk + 1][1]);
            unsigned ph3 = pk2(s[2 * kk + 1][2], s[2 * kk + 1][3]);
            unsigned pl0 = pk2(s[2 * kk][0] - blo(ph0), s[2 * kk][1] - bhi(ph0));
            unsigned pl1 = pk2(s[2 * kk][2] - blo(ph1), s[2 * kk][3] - bhi(ph1));
            unsigned pl2 = pk2(s[2 * kk + 1][0] - blo(ph2), s[2 * kk + 1][1] - bhi(ph2));
            unsigned pl3 = pk2(s[2 * kk + 1][2] - blo(ph3), s[2 * kk + 1][3] - bhi(ph3));

            int sel = lane >> 3;
            int lrw = lane & 7;
            int vrow = kk * 16 + (sel & 1) * 8 + lrw;
            int coff = (sel >> 1) * 8;

#pragma unroll
            for (int t = 0; t < 16; t += 2) {
                unsigned addr_h = smb + VHI_OFF * 4u + (unsigned)(vrow * 272 + (t * 8 + coff) * 2);
                unsigned addr_l = smb + VLO_OFF * 4u + (unsigned)(vrow * 272 + (t * 8 + coff) * 2);
                unsigned vh0, vh1, vh2, vh3, vl0, vl1, vl2, vl3;
                asm volatile("ldmatrix.sync.aligned.m8n8.x4.trans.shared.b16 {%0,%1,%2,%3}, [%4];"
                             : "=r"(vh0), "=r"(vh1), "=r"(vh2), "=r"(vh3) : "r"(addr_h));
                asm volatile("ldmatrix.sync.aligned.m8n8.x4.trans.shared.b16 {%0,%1,%2,%3}, [%4];"
                             : "=r"(vl0), "=r"(vl1), "=r"(vl2), "=r"(vl3) : "r"(addr_l));
                MMA_BF16(acc[t],     ph0, ph1, ph2, ph3, vh0, vh1);
                MMA_BF16(acc[t],     ph0, ph1, ph2, ph3, vl0, vl1);
                MMA_BF16(acc[t],     pl0, pl1, pl2, pl3, vh0, vh1);
                MMA_BF16(acc[t + 1], ph0, ph1, ph2, ph3, vh2, vh3);
                MMA_BF16(acc[t + 1], ph0, ph1, ph2, ph3, vl2, vl3);
                MMA_BF16(acc[t + 1], pl0, pl1, pl2, pl3, vh2, vh3);
            }
        }
    }

    // ---- epilogue ----
    float inv0 = 1.f / l0s, inv1 = 1.f / l1s;
#pragma unroll
    for (int t = 0; t < 16; ++t) {
        int col = t * 8 + 2 * c;
        float* d0 = O + (size_t)(b * S_ + qr0) * QD_ + (size_t)h * HD_ + col;
        float* d1 = O + (size_t)(b * S_ + qr1) * QD_ + (size_t)h * HD_ + col;
        *(float2*)d0 = make_float2(acc[t][0] * inv0, acc[t][1] * inv0);
        *(float2*)d1 = make_float2(acc[t][2] * inv1, acc[t][3] * inv1);
    }
}

// ---------------------------------------------------------------------------
extern "C" void kernel_launch(void* const* d_in, const int* in_sizes, int n_in,
                              void* d_out, int out_size)
{
    const float* x     = (const float*)d_in[0];
    const float* freqs = (const float*)d_in[1];
    const float* wq    = (const float*)d_in[2];
    const float* wk    = (const float*)d_in[3];
    const float* wv    = (const float*)d_in[4];
    const float* wo    = (const float*)d_in[5];
    float* out = (float*)d_out;

    float *q, *k, *v, *attn;
    cudaGetSymbolAddress((void**)&q,    g_q);
    cudaGetSymbolAddress((void**)&k,    g_k);
    cudaGetSymbolAddress((void**)&v,    g_v);
    cudaGetSymbolAddress((void**)&attn, g_attn);

    static int attr_set = 0;
    const int gemm_smem  = 2 * STG_ * 4;          // 81920
    const int flash_smem = FLASH_SMEM_WORDS * 4;  // 139264
    if (!attr_set) {
        cudaFuncSetAttribute(gemm_bf16x3_kernel,
                             cudaFuncAttributeMaxDynamicSharedMemorySize, gemm_smem);
        cudaFuncSetAttribute(gemm_qkv_fused_kernel,
                             cudaFuncAttributeMaxDynamicSharedMemorySize, gemm_smem);
        cudaFuncSetAttribute(flash_bf16_kernel,
                             cudaFuncAttributeMaxDynamicSharedMemorySize, flash_smem);
        attr_set = 1;
    }

    // Fused QKV projection: one 768-block launch (16 Q + 4 K + 4 V n-tiles)
    gemm_qkv_fused_kernel<<<dim3(24, M_ / 128), 256, gemm_smem>>>(
        x, wq, wk, wv, q, k, v, freqs);

    // Flash attention (bf16x3 tensor-core)
    flash_bf16_kernel<<<dim3(B_ * H_, S_ / 128), 256, flash_smem>>>(q, k, v, attn);

    // Output projection (bf16x3 tensor-core)
    gemm_bf16x3_kernel<<<dim3(DIM_ / 128, M_ / 128), 256, gemm_smem>>>(
        attn, wo, out, DIM_, QD_, 0, freqs);
}

// round 13
// speedup vs baseline: 1.6391x; 1.0723x over previous
#include <cuda_runtime.h>
#include <math.h>
#include <float.h>

#define B_    2
#define S_    2048
#define DIM_  2048
#define H_    16
#define KVH_  4
#define HD_   128
#define G_    4
#define M_    (B_*S_)          // 4096 rows total
#define QD_   (H_*HD_)         // 2048
#define KD_   (KVH_*HD_)       // 512

// Scratch (device globals -- no allocation)
__device__ float g_q[(size_t)M_*QD_];     // [b,s,h,hd]
__device__ float g_k[(size_t)M_*KD_];     // [b,s,kvh,hd]
__device__ float g_v[(size_t)M_*KD_];
__device__ float g_attn[(size_t)M_*QD_];  // [b,s,h,hd]

// ---------------------------------------------------------------------------
// helpers
// ---------------------------------------------------------------------------
__device__ __forceinline__ unsigned pk2(float lo_elem, float hi_elem) {
    unsigned d;
    asm("cvt.rn.bf16x2.f32 %0, %1, %2;" : "=r"(d) : "f"(hi_elem), "f"(lo_elem));
    return d;
}
__device__ __forceinline__ float blo(unsigned u) { return __uint_as_float(u << 16); }
__device__ __forceinline__ float bhi(unsigned u) { return __uint_as_float(u & 0xffff0000u); }

#define MMA_BF16(d, a0, a1, a2, a3, b0, b1) \
    asm volatile("mma.sync.aligned.m16n8k16.row.col.f32.bf16.bf16.f32 " \
                 "{%0,%1,%2,%3},{%4,%5,%6,%7},{%8,%9},{%0,%1,%2,%3};" \
                 : "+f"(d[0]), "+f"(d[1]), "+f"(d[2]), "+f"(d[3]) \
                 : "r"(a0), "r"(a1), "r"(a2), "r"(a3), "r"(b0), "r"(b1))

#define LDSM4(r0, r1, r2, r3, addr) \
    asm volatile("ldmatrix.sync.aligned.m8n8.x4.shared.b16 {%0,%1,%2,%3}, [%4];" \
                 : "=r"(r0), "=r"(r1), "=r"(r2), "=r"(r3) : "r"(addr))

// ---------------------------------------------------------------------------
// bf16x3 tensor-core GEMM body: C[M,N] = A[M,K] * W[N,K]^T (fp32-accurate).
// CTA tile 128(M) x 256(N), k-block 32, 256 threads (8 warps 2x4),
// warp tile 64x64. hi/lo bf16 split at smem-fill; D += Ah*Bh + Ah*Bl + Al*Bh.
// Register-prefetch double buffer; ldmatrix.x4 fragment loads.
// smem words (u32 = bf16x2), row stride 20 (16 data + 4 pad):
//   per stage: AHI[128][20] ALO[128][20] BHI[256][20] BLO[256][20] = 15360 w.
// 2 stages = 120KB -> 1 CTA/SM. Bank check: rows at 20-word spacing hit
// {0,20,8,28,16,4,24,12} 16B chunks = all 32 banks, conflict-free.
// ---------------------------------------------------------------------------
#define RS_    20
#define A2HI   0
#define A2LO   2560
#define B2HI   5120
#define B2LO   10240
#define STG2   15360
#define GEMM_SMEM (2 * STG2 * 4)

__device__ __forceinline__ void gemm_bf16x3_body(
    unsigned* smw,
    const float* __restrict__ A, const float* __restrict__ W,
    float* __restrict__ C, int Nn, int Kn, int m0, int n0,
    int do_rope, const float* __restrict__ freqs)
{
    const unsigned smb = (unsigned)__cvta_generic_to_shared(smw);
    const int tid  = threadIdx.x;
    const int lane = tid & 31;
    const int warp = tid >> 5;
    const int warpM = (warp >> 2) * 64;   // 0 or 64
    const int warpN = (warp & 3) * 64;    // 0,64,128,192
    const int r = lane >> 2;              // 0..7
    const int c = lane & 3;               // 0..3
    const int grp = lane >> 3;            // ldmatrix matrix selector
    const int lr  = lane & 7;             // row within 8

    const int lrow = tid >> 3;            // 0..31
    const int lg   = tid & 7;             // k float4 group

    float acc[4][8][4];
#pragma unroll
    for (int i = 0; i < 4; ++i)
#pragma unroll
        for (int j = 0; j < 8; ++j)
#pragma unroll
            for (int t = 0; t < 4; ++t) acc[i][j][t] = 0.f;

    const int NT = Kn >> 5;

    float4 pa[4], pb[8];

    auto issue_loads = [&](int it) {
        size_t k0 = (size_t)it * 32 + lg * 4;
#pragma unroll
        for (int i = 0; i < 4; ++i) {
            int rr = lrow + i * 32;
            pa[i] = *(const float4*)&A[(size_t)(m0 + rr) * Kn + k0];
        }
#pragma unroll
        for (int i = 0; i < 8; ++i) {
            int rr = lrow + i * 32;
            pb[i] = *(const float4*)&W[(size_t)(n0 + rr) * Kn + k0];
        }
    };

    auto store_tile = [&](int p) {
        unsigned* base = smw + p * STG2;
#pragma unroll
        for (int i = 0; i < 4; ++i) {
            int rr = lrow + i * 32;
            int w = rr * RS_ + lg * 2;
            unsigned h0 = pk2(pa[i].x, pa[i].y), h1 = pk2(pa[i].z, pa[i].w);
            *(uint2*)&base[A2HI + w] = make_uint2(h0, h1);
            *(uint2*)&base[A2LO + w] = make_uint2(
                pk2(pa[i].x - blo(h0), pa[i].y - bhi(h0)),
                pk2(pa[i].z - blo(h1), pa[i].w - bhi(h1)));
        }
#pragma unroll
        for (int i = 0; i < 8; ++i) {
            int rr = lrow + i * 32;
            int w = rr * RS_ + lg * 2;
            unsigned g0 = pk2(pb[i].x, pb[i].y), g1 = pk2(pb[i].z, pb[i].w);
            *(uint2*)&base[B2HI + w] = make_uint2(g0, g1);
            *(uint2*)&base[B2LO + w] = make_uint2(
                pk2(pb[i].x - blo(g0), pb[i].y - bhi(g0)),
                pk2(pb[i].z - blo(g1), pb[i].w - bhi(g1)));
        }
    };

    issue_loads(0);
    store_tile(0);
    __syncthreads();

    for (int it = 0; it < NT; ++it) {
        if (it + 1 < NT) issue_loads(it + 1);

        const unsigned sbase = smb + (unsigned)((it & 1) * STG2 * 4);
#pragma unroll
        for (int kk = 0; kk < 2; ++kk) {
            // B fragments: 4 bp groups (16 cols each) x (hi, lo)
            unsigned bh_[4][4], bl_[4][4];
#pragma unroll
            for (int bp = 0; bp < 4; ++bp) {
                unsigned baddr = sbase + B2HI * 4u +
                    (unsigned)(((warpN + bp * 16 + (grp >> 1) * 8 + lr) * RS_ + kk * 8) * 4 + (grp & 1) * 16);
                LDSM4(bh_[bp][0], bh_[bp][1], bh_[bp][2], bh_[bp][3], baddr);
                LDSM4(bl_[bp][0], bl_[bp][1], bl_[bp][2], bl_[bp][3], baddr + (B2LO - B2HI) * 4u);
            }
#pragma unroll
            for (int am = 0; am < 4; ++am) {
                unsigned aaddr = sbase +
                    (unsigned)(((warpM + am * 16 + (grp & 1) * 8 + lr) * RS_ + kk * 8) * 4 + (grp >> 1) * 16);
                unsigned ah0, ah1, ah2, ah3, al0, al1, al2, al3;
                LDSM4(ah0, ah1, ah2, ah3, aaddr);
                LDSM4(al0, al1, al2, al3, aaddr + A2LO * 4u);
#pragma unroll
                for (int bn = 0; bn < 8; ++bn) {
                    const int bp = bn >> 1, off = (bn & 1) * 2;
                    MMA_BF16(acc[am][bn], ah0, ah1, ah2, ah3, bh_[bp][off], bh_[bp][off + 1]);
                    MMA_BF16(acc[am][bn], ah0, ah1, ah2, ah3, bl_[bp][off], bl_[bp][off + 1]);
                    MMA_BF16(acc[am][bn], al0, al1, al2, al3, bh_[bp][off], bh_[bp][off + 1]);
                }
            }
        }

        if (it + 1 < NT) store_tile((it + 1) & 1);
        __syncthreads();
    }

    // epilogue (optionally fused RoPE: output pair (n1, n1+1) is a rope pair)
#pragma unroll
    for (int am = 0; am < 4; ++am) {
        int m1 = m0 + warpM + am * 16 + r;
#pragma unroll
        for (int bn = 0; bn < 8; ++bn) {
            int n1 = n0 + warpN + bn * 8 + 2 * c;
            float2 v0 = make_float2(acc[am][bn][0], acc[am][bn][1]);
            float2 v1 = make_float2(acc[am][bn][2], acc[am][bn][3]);
            if (do_rope) {
                int j = (n1 & (HD_ - 1)) >> 1;
                int s0 = m1 & (S_ - 1);
                int s1 = (m1 + 8) & (S_ - 1);
                float2 cs0 = *(const float2*)&freqs[((size_t)s0 * 64 + j) * 2];
                float2 cs1 = *(const float2*)&freqs[((size_t)s1 * 64 + j) * 2];
                v0 = make_float2(v0.x * cs0.x - v0.y * cs0.y,
                                 v0.x * cs0.y + v0.y * cs0.x);
                v1 = make_float2(v1.x * cs1.x - v1.y * cs1.y,
                                 v1.x * cs1.y + v1.y * cs1.x);
            }
            *(float2*)&C[(size_t)m1 * Nn + n1] = v0;
            *(float2*)&C[(size_t)(m1 + 8) * Nn + n1] = v1;
        }
    }
}

// Generic GEMM (used for the output projection)
__global__ __launch_bounds__(256, 1) void gemm_bf16x3_kernel(
    const float* __restrict__ A, const float* __restrict__ W,
    float* __restrict__ C, int Nn, int Kn,
    int do_rope, const float* __restrict__ freqs)
{
    extern __shared__ unsigned smw[];
    gemm_bf16x3_body(smw, A, W, C, Nn, Kn,
                     blockIdx.y * 128, blockIdx.x * 256, do_rope, freqs);
}

// Fused QKV GEMM: one launch covers wq (8 n-tiles of 256), wk (2), wv (2).
__global__ __launch_bounds__(256, 1) void gemm_qkv_fused_kernel(
    const float* __restrict__ X,
    const float* __restrict__ WQ, const float* __restrict__ WK,
    const float* __restrict__ WV,
    float* __restrict__ Qo, float* __restrict__ Ko, float* __restrict__ Vo,
    const float* __restrict__ freqs)
{
    extern __shared__ unsigned smw[];
    const int bx = blockIdx.x;
    const float* W;
    float* C;
    int Nn, n0, rope;
    if (bx < 8)       { W = WQ; C = Qo; Nn = QD_; n0 = bx * 256;        rope = 1; }
    else if (bx < 10) { W = WK; C = Ko; Nn = KD_; n0 = (bx - 8) * 256;  rope = 1; }
    else              { W = WV; C = Vo; Nn = KD_; n0 = (bx - 10) * 256; rope = 0; }
    gemm_bf16x3_body(smw, X, W, C, Nn, DIM_, blockIdx.y * 128, n0, rope, freqs);
}

// ---------------------------------------------------------------------------
// Flash attention, bf16x3 tensor-core version (causal, GQA).
// Block: 256 thr (8 warps). q-tile 128 rows, kv-tile 64. Warp w owns q rows
// [w*16, w*16+16). Q/K/V split hi/lo bf16 in smem; P kept in registers.
// ---------------------------------------------------------------------------
#define QHI_OFF 0
#define QLO_OFF 8704
#define KHI_OFF 17408
#define KLO_OFF 21760
#define VHI_OFF 26112
#define VLO_OFF 30464
#define FLASH_SMEM_WORDS 34816

__global__ __launch_bounds__(256, 1) void flash_bf16_kernel(
    const float* __restrict__ Q, const float* __restrict__ K,
    const float* __restrict__ V, float* __restrict__ O)
{
    extern __shared__ unsigned smw[];
    unsigned* QHI = smw + QHI_OFF;
    unsigned* QLO = smw + QLO_OFF;
    unsigned* KHI = smw + KHI_OFF;
    unsigned* KLO = smw + KLO_OFF;
    unsigned* VHI = smw + VHI_OFF;
    unsigned* VLO = smw + VLO_OFF;
    const unsigned smb = (unsigned)__cvta_generic_to_shared(smw);

    const int bh = blockIdx.x;                 // 0..31
    const int ib = (int)gridDim.y - 1 - (int)blockIdx.y;  // heavy tiles first
    const int b  = bh / H_;
    const int h  = bh % H_;
    const int kv = h / G_;

    const float* Qg = Q + (size_t)b * S_ * QD_ + (size_t)h * HD_;
    const float* Kg = K + (size_t)b * S_ * KD_ + (size_t)kv * HD_;
    const float* Vg = V + (size_t)b * S_ * KD_ + (size_t)kv * HD_;

    const int tid  = threadIdx.x;
    const int lane = tid & 31;
    const int warp = tid >> 5;
    const int r = lane >> 2;      // 0..7
    const int c = lane & 3;       // 0..3
    const int grp = lane >> 3;    // ldmatrix selector
    const int lr  = lane & 7;
    const float scale = 0.08838834764831845f;

    // ---- load + convert Q tile (128 x 128) once ----
    for (int i = tid; i < 128 * 32; i += 256) {
        int row = i >> 5;
        int hd4 = (i & 31) * 4;
        float4 f = *(const float4*)&Qg[(size_t)(ib * 128 + row) * QD_ + hd4];
        unsigned h0 = pk2(f.x, f.y), h1 = pk2(f.z, f.w);
        unsigned l0 = pk2(f.x - blo(h0), f.y - bhi(h0));
        unsigned l1 = pk2(f.z - blo(h1), f.w - bhi(h1));
        int w = row * 68 + (hd4 >> 1);
        QHI[w] = h0; QHI[w + 1] = h1;
        QLO[w] = l0; QLO[w + 1] = l1;
    }

    float m0 = -1e30f, m1 = -1e30f, l0s = 0.f, l1s = 0.f;
    float acc[16][4];
#pragma unroll
    for (int t = 0; t < 16; ++t)
#pragma unroll
        for (int e = 0; e < 4; ++e) acc[t][e] = 0.f;

    const int qr0 = ib * 128 + warp * 16 + r;
    const int qr1 = qr0 + 8;
    const int jmax = 2 * ib + 1;

    for (int j = 0; j <= jmax; ++j) {
        __syncthreads();
        // ---- load + convert K and V tiles (64 x 128 each) ----
        for (int i = tid; i < 64 * 32; i += 256) {
            int row = i >> 5;
            int hd4 = (i & 31) * 4;
            int w = row * 68 + (hd4 >> 1);
            float4 f = *(const float4*)&Kg[(size_t)(j * 64 + row) * KD_ + hd4];
            unsigned h0 = pk2(f.x, f.y), h1 = pk2(f.z, f.w);
            KHI[w] = h0; KHI[w + 1] = h1;
            KLO[w]     = pk2(f.x - blo(h0), f.y - bhi(h0));
            KLO[w + 1] = pk2(f.z - blo(h1), f.w - bhi(h1));
            float4 g = *(const float4*)&Vg[(size_t)(j * 64 + row) * KD_ + hd4];
            unsigned v0 = pk2(g.x, g.y), v1 = pk2(g.z, g.w);
            VHI[w] = v0; VHI[w + 1] = v1;
            VLO[w]     = pk2(g.x - blo(v0), g.y - bhi(v0));
            VLO[w + 1] = pk2(g.z - blo(v1), g.w - bhi(v1));
        }
        __syncthreads();

        // ---- QK^T (ldmatrix fragments) ----
        float s[8][4];
#pragma unroll
        for (int bn = 0; bn < 8; ++bn)
#pragma unroll
            for (int e = 0; e < 4; ++e) s[bn][e] = 0.f;

#pragma unroll
        for (int kk = 0; kk < 8; ++kk) {
            unsigned qaddr = smb +
                (unsigned)(((warp * 16 + (grp & 1) * 8 + lr) * 68 + kk * 8) * 4 + (grp >> 1) * 16);
            unsigned ah0, ah1, ah2, ah3, al0, al1, al2, al3;
            LDSM4(ah0, ah1, ah2, ah3, qaddr);
            LDSM4(al0, al1, al2, al3, qaddr + QLO_OFF * 4u);
#pragma unroll
            for (int bp = 0; bp < 4; ++bp) {
                unsigned kaddr = smb + KHI_OFF * 4u +
                    (unsigned)(((bp * 16 + (grp >> 1) * 8 + lr) * 68 + kk * 8) * 4 + (grp & 1) * 16);
                unsigned kh[4], kl[4];
                LDSM4(kh[0], kh[1], kh[2], kh[3], kaddr);
                LDSM4(kl[0], kl[1], kl[2], kl[3], kaddr + (KLO_OFF - KHI_OFF) * 4u);
                MMA_BF16(s[2 * bp],     ah0, ah1, ah2, ah3, kh[0], kh[1]);
                MMA_BF16(s[2 * bp],     ah0, ah1, ah2, ah3, kl[0], kl[1]);
                MMA_BF16(s[2 * bp],     al0, al1, al2, al3, kh[0], kh[1]);
                MMA_BF16(s[2 * bp + 1], ah0, ah1, ah2, ah3, kh[2], kh[3]);
                MMA_BF16(s[2 * bp + 1], ah0, ah1, ah2, ah3, kl[2], kl[3]);
                MMA_BF16(s[2 * bp + 1], al0, al1, al2, al3, kh[2], kh[3]);
            }
        }

        // ---- scale, mask, online softmax ----
        const bool need_mask = (j >= 2 * ib);
        float vmax0 = -1e30f, vmax1 = -1e30f;
#pragma unroll
        for (int bn = 0; bn < 8; ++bn) {
#pragma unroll
            for (int e = 0; e < 2; ++e) {
                int col = j * 64 + bn * 8 + 2 * c + e;
                float v0 = s[bn][e] * scale;
                if (need_mask && col > qr0) v0 = -1e30f;
                s[bn][e] = v0;
                vmax0 = fmaxf(vmax0, v0);
                float v1 = s[bn][2 + e] * scale;
                if (need_mask && col > qr1) v1 = -1e30f;
                s[bn][2 + e] = v1;
                vmax1 = fmaxf(vmax1, v1);
            }
        }
        vmax0 = fmaxf(vmax0, __shfl_xor_sync(0xffffffffu, vmax0, 1));
        vmax0 = fmaxf(vmax0, __shfl_xor_sync(0xffffffffu, vmax0, 2));
        vmax1 = fmaxf(vmax1, __shfl_xor_sync(0xffffffffu, vmax1, 1));
        vmax1 = fmaxf(vmax1, __shfl_xor_sync(0xffffffffu, vmax1, 2));

        float mn0 = fmaxf(m0, vmax0), mn1 = fmaxf(m1, vmax1);
        float alpha0 = __expf(m0 - mn0), alpha1 = __expf(m1 - mn1);
        m0 = mn0; m1 = mn1;

        float rs0 = 0.f, rs1 = 0.f;
#pragma unroll
        for (int bn = 0; bn < 8; ++bn) {
#pragma unroll
            for (int e = 0; e < 2; ++e) {
                float p0 = __expf(s[bn][e] - mn0);
                s[bn][e] = p0; rs0 += p0;
                float p1 = __expf(s[bn][2 + e] - mn1);
                s[bn][2 + e] = p1; rs1 += p1;
            }
        }
        rs0 += __shfl_xor_sync(0xffffffffu, rs0, 1);
        rs0 += __shfl_xor_sync(0xffffffffu, rs0, 2);
        rs1 += __shfl_xor_sync(0xffffffffu, rs1, 1);
        rs1 += __shfl_xor_sync(0xffffffffu, rs1, 2);
        l0s = l0s * alpha0 + rs0;
        l1s = l1s * alpha1 + rs1;

#pragma unroll
        for (int t = 0; t < 16; ++t) {
            acc[t][0] *= alpha0; acc[t][1] *= alpha0;
            acc[t][2] *= alpha1; acc[t][3] *= alpha1;
        }

        // ---- PV ----
#pragma unroll
        for (int kk = 0; kk < 4; ++kk) {
            unsigned ph0 = pk2(s[2 * kk][0], s[2 * kk][1]);
            unsigned ph1 = pk2(s[2 * kk][2], s[2 * kk][3]);
            unsigned ph2 = pk2(s[2 * kk + 1][0], s[2 * kk + 1][1]);
            unsigned ph3 = pk2(s[2 * kk + 1][2], s[2 * kk + 1][3]);
            unsigned pl0 = pk2(s[2 * kk][0] - blo(ph0), s[2 * kk][1] - bhi(ph0));
            unsigned pl1 = pk2(s[2 * kk][2] - blo(ph1), s[2 * kk][3] - bhi(ph1));
            unsigned pl2 = pk2(s[2 * kk + 1][0] - blo(ph2), s[2 * kk + 1][1] - bhi(ph2));
            unsigned pl3 = pk2(s[2 * kk + 1][2] - blo(ph3), s[2 * kk + 1][3] - bhi(ph3));

            int sel = lane >> 3;
            int lrw = lane & 7;
            int vrow = kk * 16 + (sel & 1) * 8 + lrw;
            int coff = (sel >> 1) * 8;

#pragma unroll
            for (int t = 0; t < 16; t += 2) {
                unsigned addr_h = smb + VHI_OFF * 4u + (unsigned)(vrow * 272 + (t * 8 + coff) * 2);
                unsigned addr_l = smb + VLO_OFF * 4u + (unsigned)(vrow * 272 + (t * 8 + coff) * 2);
                unsigned vh0, vh1, vh2, vh3, vl0, vl1, vl2, vl3;
                asm volatile("ldmatrix.sync.aligned.m8n8.x4.trans.shared.b16 {%0,%1,%2,%3}, [%4];"
                             : "=r"(vh0), "=r"(vh1), "=r"(vh2), "=r"(vh3) : "r"(addr_h));
                asm volatile("ldmatrix.sync.aligned.m8n8.x4.trans.shared.b16 {%0,%1,%2,%3}, [%4];"
                             : "=r"(vl0), "=r"(vl1), "=r"(vl2), "=r"(vl3) : "r"(addr_l));
                MMA_BF16(acc[t],     ph0, ph1, ph2, ph3, vh0, vh1);
                MMA_BF16(acc[t],     ph0, ph1, ph2, ph3, vl0, vl1);
                MMA_BF16(acc[t],     pl0, pl1, pl2, pl3, vh0, vh1);
                MMA_BF16(acc[t + 1], ph0, ph1, ph2, ph3, vh2, vh3);
                MMA_BF16(acc[t + 1], ph0, ph1, ph2, ph3, vl2, vl3);
                MMA_BF16(acc[t + 1], pl0, pl1, pl2, pl3, vh2, vh3);
            }
        }
    }

    // ---- epilogue ----
    float inv0 = 1.f / l0s, inv1 = 1.f / l1s;
#pragma unroll
    for (int t = 0; t < 16; ++t) {
        int col = t * 8 + 2 * c;
        float* d0 = O + (size_t)(b * S_ + qr0) * QD_ + (size_t)h * HD_ + col;
        float* d1 = O + (size_t)(b * S_ + qr1) * QD_ + (size_t)h * HD_ + col;
        *(float2*)d0 = make_float2(acc[t][0] * inv0, acc[t][1] * inv0);
        *(float2*)d1 = make_float2(acc[t][2] * inv1, acc[t][3] * inv1);
    }
}

// ---------------------------------------------------------------------------
extern "C" void kernel_launch(void* const* d_in, const int* in_sizes, int n_in,
                              void* d_out, int out_size)
{
    const float* x     = (const float*)d_in[0];
    const float* freqs = (const float*)d_in[1];
    const float* wq    = (const float*)d_in[2];
    const float* wk    = (const float*)d_in[3];
    const float* wv    = (const float*)d_in[4];
    const float* wo    = (const float*)d_in[5];
    float* out = (float*)d_out;

    float *q, *k, *v, *attn;
    cudaGetSymbolAddress((void**)&q,    g_q);
    cudaGetSymbolAddress((void**)&k,    g_k);
    cudaGetSymbolAddress((void**)&v,    g_v);
    cudaGetSymbolAddress((void**)&attn, g_attn);

    static int attr_set = 0;
    const int flash_smem = FLASH_SMEM_WORDS * 4;  // 139264
    if (!attr_set) {
        cudaFuncSetAttribute(gemm_bf16x3_kernel,
                             cudaFuncAttributeMaxDynamicSharedMemorySize, GEMM_SMEM);
        cudaFuncSetAttribute(gemm_qkv_fused_kernel,
                             cudaFuncAttributeMaxDynamicSharedMemorySize, GEMM_SMEM);
        cudaFuncSetAttribute(flash_bf16_kernel,
                             cudaFuncAttributeMaxDynamicSharedMemorySize, flash_smem);
        attr_set = 1;
    }

    // Fused QKV projection: 12x32 = 384 blocks (8 Q + 2 K + 2 V n-tiles of 256)
    gemm_qkv_fused_kernel<<<dim3(12, M_ / 128), 256, GEMM_SMEM>>>(
        x, wq, wk, wv, q, k, v, freqs);

    // Flash attention (bf16x3 tensor-core)
    flash_bf16_kernel<<<dim3(B_ * H_, S_ / 128), 256, flash_smem>>>(q, k, v, attn);

    // Output projection (bf16x3 tensor-core)
    gemm_bf16x3_kernel<<<dim3(DIM_ / 256, M_ / 128), 256, GEMM_SMEM>>>(
        attn, wo, out, DIM_, QD_, 0, freqs);
}

// round 16
// speedup vs baseline: 1.6519x; 1.0078x over previous
#include <cuda_runtime.h>
#include <math.h>
#include <float.h>

#define B_    2
#define S_    2048
#define DIM_  2048
#define H_    16
#define KVH_  4
#define HD_   128
#define G_    4
#define M_    (B_*S_)          // 4096 rows total
#define QD_   (H_*HD_)         // 2048
#define KD_   (KVH_*HD_)       // 512

// Scratch (device globals -- no allocation)
__device__ float g_q[(size_t)M_*QD_];     // [b,s,h,hd]
__device__ float g_k[(size_t)M_*KD_];     // [b,s,kvh,hd]
__device__ float g_v[(size_t)M_*KD_];
__device__ float g_attn[(size_t)M_*QD_];  // [b,s,h,hd]

// ---------------------------------------------------------------------------
// helpers
// ---------------------------------------------------------------------------
__device__ __forceinline__ unsigned pk2(float lo_elem, float hi_elem) {
    unsigned d;
    asm("cvt.rn.bf16x2.f32 %0, %1, %2;" : "=r"(d) : "f"(hi_elem), "f"(lo_elem));
    return d;
}
__device__ __forceinline__ float blo(unsigned u) { return __uint_as_float(u << 16); }
__device__ __forceinline__ float bhi(unsigned u) { return __uint_as_float(u & 0xffff0000u); }

#define MMA_BF16(d, a0, a1, a2, a3, b0, b1) \
    asm volatile("mma.sync.aligned.m16n8k16.row.col.f32.bf16.bf16.f32 " \
                 "{%0,%1,%2,%3},{%4,%5,%6,%7},{%8,%9},{%0,%1,%2,%3};" \
                 : "+f"(d[0]), "+f"(d[1]), "+f"(d[2]), "+f"(d[3]) \
                 : "r"(a0), "r"(a1), "r"(a2), "r"(a3), "r"(b0), "r"(b1))

#define LDSM4(r0, r1, r2, r3, addr) \
    asm volatile("ldmatrix.sync.aligned.m8n8.x4.shared.b16 {%0,%1,%2,%3}, [%4];" \
                 : "=r"(r0), "=r"(r1), "=r"(r2), "=r"(r3) : "r"(addr))

// ---------------------------------------------------------------------------
// bf16x3 tensor-core GEMM body: C[M,N] = A[M,K] * W[N,K]^T (fp32-accurate).
// CTA tile 128(M) x 256(N), k-block 32, 256 threads (8 warps 2x4),
// warp tile 64x64. hi/lo bf16 split at smem-fill; D += Ah*Bh + Ah*Bl + Al*Bh.
// Register-prefetch double buffer; ldmatrix.x4 fragment loads.
// ---------------------------------------------------------------------------
#define RS_    20
#define A2HI   0
#define A2LO   2560
#define B2HI   5120
#define B2LO   10240
#define STG2   15360
#define GEMM_SMEM (2 * STG2 * 4)

__device__ __forceinline__ void gemm_bf16x3_body(
    unsigned* smw,
    const float* __restrict__ A, const float* __restrict__ W,
    float* __restrict__ C, int Nn, int Kn, int m0, int n0,
    int do_rope, const float* __restrict__ freqs)
{
    const unsigned smb = (unsigned)__cvta_generic_to_shared(smw);
    const int tid  = threadIdx.x;
    const int lane = tid & 31;
    const int warp = tid >> 5;
    const int warpM = (warp >> 2) * 64;   // 0 or 64
    const int warpN = (warp & 3) * 64;    // 0,64,128,192
    const int r = lane >> 2;              // 0..7
    const int c = lane & 3;               // 0..3
    const int grp = lane >> 3;            // ldmatrix matrix selector
    const int lr  = lane & 7;             // row within 8

    const int lrow = tid >> 3;            // 0..31
    const int lg   = tid & 7;             // k float4 group

    float acc[4][8][4];
#pragma unroll
    for (int i = 0; i < 4; ++i)
#pragma unroll
        for (int j = 0; j < 8; ++j)
#pragma unroll
            for (int t = 0; t < 4; ++t) acc[i][j][t] = 0.f;

    const int NT = Kn >> 5;

    float4 pa[4], pb[8];

    auto issue_loads = [&](int it) {
        size_t k0 = (size_t)it * 32 + lg * 4;
#pragma unroll
        for (int i = 0; i < 4; ++i) {
            int rr = lrow + i * 32;
            pa[i] = *(const float4*)&A[(size_t)(m0 + rr) * Kn + k0];
        }
#pragma unroll
        for (int i = 0; i < 8; ++i) {
            int rr = lrow + i * 32;
            pb[i] = *(const float4*)&W[(size_t)(n0 + rr) * Kn + k0];
        }
    };

    auto store_tile = [&](int p) {
        unsigned* base = smw + p * STG2;
#pragma unroll
        for (int i = 0; i < 4; ++i) {
            int rr = lrow + i * 32;
            int w = rr * RS_ + lg * 2;
            unsigned h0 = pk2(pa[i].x, pa[i].y), h1 = pk2(pa[i].z, pa[i].w);
            *(uint2*)&base[A2HI + w] = make_uint2(h0, h1);
            *(uint2*)&base[A2LO + w] = make_uint2(
                pk2(pa[i].x - blo(h0), pa[i].y - bhi(h0)),
                pk2(pa[i].z - blo(h1), pa[i].w - bhi(h1)));
        }
#pragma unroll
        for (int i = 0; i < 8; ++i) {
            int rr = lrow + i * 32;
            int w = rr * RS_ + lg * 2;
            unsigned g0 = pk2(pb[i].x, pb[i].y), g1 = pk2(pb[i].z, pb[i].w);
            *(uint2*)&base[B2HI + w] = make_uint2(g0, g1);
            *(uint2*)&base[B2LO + w] = make_uint2(
                pk2(pb[i].x - blo(g0), pb[i].y - bhi(g0)),
                pk2(pb[i].z - blo(g1), pb[i].w - bhi(g1)));
        }
    };

    issue_loads(0);
    store_tile(0);
    __syncthreads();

    for (int it = 0; it < NT; ++it) {
        if (it + 1 < NT) issue_loads(it + 1);

        const unsigned sbase = smb + (unsigned)((it & 1) * STG2 * 4);
#pragma unroll
        for (int kk = 0; kk < 2; ++kk) {
            unsigned bh_[4][4], bl_[4][4];
#pragma unroll
            for (int bp = 0; bp < 4; ++bp) {
                unsigned baddr = sbase + B2HI * 4u +
                    (unsigned)(((warpN + bp * 16 + (grp >> 1) * 8 + lr) * RS_ + kk * 8) * 4 + (grp & 1) * 16);
                LDSM4(bh_[bp][0], bh_[bp][1], bh_[bp][2], bh_[bp][3], baddr);
                LDSM4(bl_[bp][0], bl_[bp][1], bl_[bp][2], bl_[bp][3], baddr + (B2LO - B2HI) * 4u);
            }
#pragma unroll
            for (int am = 0; am < 4; ++am) {
                unsigned aaddr = sbase +
                    (unsigned)(((warpM + am * 16 + (grp & 1) * 8 + lr) * RS_ + kk * 8) * 4 + (grp >> 1) * 16);
                unsigned ah0, ah1, ah2, ah3, al0, al1, al2, al3;
                LDSM4(ah0, ah1, ah2, ah3, aaddr);
                LDSM4(al0, al1, al2, al3, aaddr + A2LO * 4u);
#pragma unroll
                for (int bn = 0; bn < 8; ++bn) {
                    const int bp = bn >> 1, off = (bn & 1) * 2;
                    MMA_BF16(acc[am][bn], ah0, ah1, ah2, ah3, bh_[bp][off], bh_[bp][off + 1]);
                    MMA_BF16(acc[am][bn], ah0, ah1, ah2, ah3, bl_[bp][off], bl_[bp][off + 1]);
                    MMA_BF16(acc[am][bn], al0, al1, al2, al3, bh_[bp][off], bh_[bp][off + 1]);
                }
            }
        }

        if (it + 1 < NT) store_tile((it + 1) & 1);
        __syncthreads();
    }

    // epilogue (optionally fused RoPE)
#pragma unroll
    for (int am = 0; am < 4; ++am) {
        int m1 = m0 + warpM + am * 16 + r;
#pragma unroll
        for (int bn = 0; bn < 8; ++bn) {
            int n1 = n0 + warpN + bn * 8 + 2 * c;
            float2 v0 = make_float2(acc[am][bn][0], acc[am][bn][1]);
            float2 v1 = make_float2(acc[am][bn][2], acc[am][bn][3]);
            if (do_rope) {
                int j = (n1 & (HD_ - 1)) >> 1;
                int s0 = m1 & (S_ - 1);
                int s1 = (m1 + 8) & (S_ - 1);
                float2 cs0 = *(const float2*)&freqs[((size_t)s0 * 64 + j) * 2];
                float2 cs1 = *(const float2*)&freqs[((size_t)s1 * 64 + j) * 2];
                v0 = make_float2(v0.x * cs0.x - v0.y * cs0.y,
                                 v0.x * cs0.y + v0.y * cs0.x);
                v1 = make_float2(v1.x * cs1.x - v1.y * cs1.y,
                                 v1.x * cs1.y + v1.y * cs1.x);
            }
            *(float2*)&C[(size_t)m1 * Nn + n1] = v0;
            *(float2*)&C[(size_t)(m1 + 8) * Nn + n1] = v1;
        }
    }
}

// Generic GEMM (used for the output projection)
__global__ __launch_bounds__(256, 1) void gemm_bf16x3_kernel(
    const float* __restrict__ A, const float* __restrict__ W,
    float* __restrict__ C, int Nn, int Kn,
    int do_rope, const float* __restrict__ freqs)
{
    extern __shared__ unsigned smw[];
    gemm_bf16x3_body(smw, A, W, C, Nn, Kn,
                     blockIdx.y * 128, blockIdx.x * 256, do_rope, freqs);
}

// Fused QKV GEMM: one launch covers wq (8 n-tiles of 256), wk (2), wv (2).
__global__ __launch_bounds__(256, 1) void gemm_qkv_fused_kernel(
    const float* __restrict__ X,
    const float* __restrict__ WQ, const float* __restrict__ WK,
    const float* __restrict__ WV,
    float* __restrict__ Qo, float* __restrict__ Ko, float* __restrict__ Vo,
    const float* __restrict__ freqs)
{
    extern __shared__ unsigned smw[];
    const int bx = blockIdx.x;
    const float* W;
    float* C;
    int Nn, n0, rope;
    if (bx < 8)       { W = WQ; C = Qo; Nn = QD_; n0 = bx * 256;        rope = 1; }
    else if (bx < 10) { W = WK; C = Ko; Nn = KD_; n0 = (bx - 8) * 256;  rope = 1; }
    else              { W = WV; C = Vo; Nn = KD_; n0 = (bx - 10) * 256; rope = 0; }
    gemm_bf16x3_body(smw, X, W, C, Nn, DIM_, blockIdx.y * 128, n0, rope, freqs);
}

// ---------------------------------------------------------------------------
// Flash attention, GQA-packed bf16x3 (causal). One block = one kv-head x a
// 32-position q-window, with all G_=4 sharing q-heads packed as 128 virtual
// q-rows (head*32 + pos). K/V tiles loaded+converted ONCE for 4 heads.
// Warp w owns virtual rows [w*16, w*16+16): head = w>>1, pos window
// (w&1)*16..+16. kv tiles j=0..ib>>1; mask only on j==jmax.
// ---------------------------------------------------------------------------
#define QHI_OFF 0
#define QLO_OFF 8704
#define KHI_OFF 17408
#define KLO_OFF 21760
#define VHI_OFF 26112
#define VLO_OFF 30464
#define FLASH_SMEM_WORDS 34816

__global__ __launch_bounds__(256, 1) void flash_bf16_kernel(
    const float* __restrict__ Q, const float* __restrict__ K,
    const float* __restrict__ V, float* __restrict__ O)
{
    extern __shared__ unsigned smw[];
    unsigned* QHI = smw + QHI_OFF;
    unsigned* QLO = smw + QLO_OFF;
    unsigned* KHI = smw + KHI_OFF;
    unsigned* KLO = smw + KLO_OFF;
    unsigned* VHI = smw + VHI_OFF;
    unsigned* VLO = smw + VLO_OFF;
    const unsigned smb = (unsigned)__cvta_generic_to_shared(smw);

    const int bkv = blockIdx.x;                // 0..7
    const int ib  = (int)gridDim.y - 1 - (int)blockIdx.y;  // 0..63, heavy first
    const int b   = bkv / KVH_;
    const int kv  = bkv % KVH_;

    const float* Kg = K + (size_t)b * S_ * KD_ + (size_t)kv * HD_;
    const float* Vg = V + (size_t)b * S_ * KD_ + (size_t)kv * HD_;

    const int tid  = threadIdx.x;
    const int lane = tid & 31;
    const int warp = tid >> 5;
    const int r = lane >> 2;      // 0..7
    const int c = lane & 3;       // 0..3
    const int grp = lane >> 3;    // ldmatrix selector
    const int lr  = lane & 7;
    const float scale = 0.08838834764831845f;

    // ---- load + convert Q (4 heads x 32 pos = 128 virtual rows x 128) ----
    for (int i = tid; i < 128 * 32; i += 256) {
        int vr  = i >> 5;                 // virtual row: head*32 + pos
        int hd4 = (i & 31) * 4;
        int hh  = vr >> 5;                // head within group 0..3
        int sp  = vr & 31;                // seq pos within window
        float4 f = *(const float4*)&Q[(size_t)(b * S_ + ib * 32 + sp) * QD_ +
                                      (size_t)(kv * G_ + hh) * HD_ + hd4];
        unsigned h0 = pk2(f.x, f.y), h1 = pk2(f.z, f.w);
        unsigned l0 = pk2(f.x - blo(h0), f.y - bhi(h0));
        unsigned l1 = pk2(f.z - blo(h1), f.w - bhi(h1));
        int w = vr * 68 + (hd4 >> 1);
        QHI[w] = h0; QHI[w + 1] = h1;
        QLO[w] = l0; QLO[w + 1] = l1;
    }

    float m0 = -1e30f, m1 = -1e30f, l0s = 0.f, l1s = 0.f;
    float acc[16][4];
#pragma unroll
    for (int t = 0; t < 16; ++t)
#pragma unroll
        for (int e = 0; e < 4; ++e) acc[t][e] = 0.f;

    const int hw  = kv * G_ + (warp >> 1);            // this warp's q-head
    const int qr0 = ib * 32 + (warp & 1) * 16 + r;    // seq row of c0,c1
    const int qr1 = qr0 + 8;
    const int jmax = ib >> 1;

    for (int j = 0; j <= jmax; ++j) {
        __syncthreads();
        // ---- load + convert K and V tiles (64 x 128 each) ----
        for (int i = tid; i < 64 * 32; i += 256) {
            int row = i >> 5;
            int hd4 = (i & 31) * 4;
            int w = row * 68 + (hd4 >> 1);
            float4 f = *(const float4*)&Kg[(size_t)(j * 64 + row) * KD_ + hd4];
            unsigned h0 = pk2(f.x, f.y), h1 = pk2(f.z, f.w);
            KHI[w] = h0; KHI[w + 1] = h1;
            KLO[w]     = pk2(f.x - blo(h0), f.y - bhi(h0));
            KLO[w + 1] = pk2(f.z - blo(h1), f.w - bhi(h1));
            float4 g = *(const float4*)&Vg[(size_t)(j * 64 + row) * KD_ + hd4];
            unsigned v0 = pk2(g.x, g.y), v1 = pk2(g.z, g.w);
            VHI[w] = v0; VHI[w + 1] = v1;
            VLO[w]     = pk2(g.x - blo(v0), g.y - bhi(v0));
            VLO[w + 1] = pk2(g.z - blo(v1), g.w - bhi(v1));
        }
        __syncthreads();

        // ---- QK^T (ldmatrix fragments) ----
        float s[8][4];
#pragma unroll
        for (int bn = 0; bn < 8; ++bn)
#pragma unroll
            for (int e = 0; e < 4; ++e) s[bn][e] = 0.f;

#pragma unroll
        for (int kk = 0; kk < 8; ++kk) {
            unsigned qaddr = smb +
                (unsigned)(((warp * 16 + (grp & 1) * 8 + lr) * 68 + kk * 8) * 4 + (grp >> 1) * 16);
            unsigned ah0, ah1, ah2, ah3, al0, al1, al2, al3;
            LDSM4(ah0, ah1, ah2, ah3, qaddr);
            LDSM4(al0, al1, al2, al3, qaddr + QLO_OFF * 4u);
#pragma unroll
            for (int bp = 0; bp < 4; ++bp) {
                unsigned kaddr = smb + KHI_OFF * 4u +
                    (unsigned)(((bp * 16 + (grp >> 1) * 8 + lr) * 68 + kk * 8) * 4 + (grp & 1) * 16);
                unsigned kh[4], kl[4];
                LDSM4(kh[0], kh[1], kh[2], kh[3], kaddr);
                LDSM4(kl[0], kl[1], kl[2], kl[3], kaddr + (KLO_OFF - KHI_OFF) * 4u);
                MMA_BF16(s[2 * bp],     ah0, ah1, ah2, ah3, kh[0], kh[1]);
                MMA_BF16(s[2 * bp],     ah0, ah1, ah2, ah3, kl[0], kl[1]);
                MMA_BF16(s[2 * bp],     al0, al1, al2, al3, kh[0], kh[1]);
                MMA_BF16(s[2 * bp + 1], ah0, ah1, ah2, ah3, kh[2], kh[3]);
                MMA_BF16(s[2 * bp + 1], ah0, ah1, ah2, ah3, kl[2], kl[3]);
                MMA_BF16(s[2 * bp + 1], al0, al1, al2, al3, kh[2], kh[3]);
            }
        }

        // ---- scale, mask, online softmax ----
        const bool need_mask = (j == jmax);
        float vmax0 = -1e30f, vmax1 = -1e30f;
#pragma unroll
        for (int bn = 0; bn < 8; ++bn) {
#pragma unroll
            for (int e = 0; e < 2; ++e) {
                int col = j * 64 + bn * 8 + 2 * c + e;
                float v0 = s[bn][e] * scale;
                if (need_mask && col > qr0) v0 = -1e30f;
                s[bn][e] = v0;
                vmax0 = fmaxf(vmax0, v0);
                float v1 = s[bn][2 + e] * scale;
                if (need_mask && col > qr1) v1 = -1e30f;
                s[bn][2 + e] = v1;
                vmax1 = fmaxf(vmax1, v1);
            }
        }
        vmax0 = fmaxf(vmax0, __shfl_xor_sync(0xffffffffu, vmax0, 1));
        vmax0 = fmaxf(vmax0, __shfl_xor_sync(0xffffffffu, vmax0, 2));
        vmax1 = fmaxf(vmax1, __shfl_xor_sync(0xffffffffu, vmax1, 1));
        vmax1 = fmaxf(vmax1, __shfl_xor_sync(0xffffffffu, vmax1, 2));

        float mn0 = fmaxf(m0, vmax0), mn1 = fmaxf(m1, vmax1);
        float alpha0 = __expf(m0 - mn0), alpha1 = __expf(m1 - mn1);
        m0 = mn0; m1 = mn1;

        float rs0 = 0.f, rs1 = 0.f;
#pragma unroll
        for (int bn = 0; bn < 8; ++bn) {
#pragma unroll
            for (int e = 0; e < 2; ++e) {
                float p0 = __expf(s[bn][e] - mn0);
                s[bn][e] = p0; rs0 += p0;
                float p1 = __expf(s[bn][2 + e] - mn1);
                s[bn][2 + e] = p1; rs1 += p1;
            }
        }
        rs0 += __shfl_xor_sync(0xffffffffu, rs0, 1);
        rs0 += __shfl_xor_sync(0xffffffffu, rs0, 2);
        rs1 += __shfl_xor_sync(0xffffffffu, rs1, 1);
        rs1 += __shfl_xor_sync(0xffffffffu, rs1, 2);
        l0s = l0s * alpha0 + rs0;
        l1s = l1s * alpha1 + rs1;

#pragma unroll
        for (int t = 0; t < 16; ++t) {
            acc[t][0] *= alpha0; acc[t][1] *= alpha0;
            acc[t][2] *= alpha1; acc[t][3] *= alpha1;
        }

        // ---- PV ----
#pragma unroll
        for (int kk = 0; kk < 4; ++kk) {
            unsigned ph0 = pk2(s[2 * kk][0], s[2 * kk][1]);
            unsigned ph1 = pk2(s[2 * kk][2], s[2 * kk][3]);
            unsigned ph2 = pk2(s[2 * kk + 1][0], s[2 * kk + 1][1]);
            unsigned ph3 = pk2(s[2 * kk + 1][2], s[2 * kk + 1][3]);
            unsigned pl0 = pk2(s[2 * kk][0] - blo(ph0), s[2 * kk][1] - bhi(ph0));
            unsigned pl1 = pk2(s[2 * kk][2] - blo(ph1), s[2 * kk][3] - bhi(ph1));
            unsigned pl2 = pk2(s[2 * kk + 1][0] - blo(ph2), s[2 * kk + 1][1] - bhi(ph2));
            unsigned pl3 = pk2(s[2 * kk + 1][2] - blo(ph3), s[2 * kk + 1][3] - bhi(ph3));

            int sel = lane >> 3;
            int lrw = lane & 7;
            int vrow = kk * 16 + (sel & 1) * 8 + lrw;
            int coff = (sel >> 1) * 8;

#pragma unroll
            for (int t = 0; t < 16; t += 2) {
                unsigned addr_h = smb + VHI_OFF * 4u + (unsigned)(vrow * 272 + (t * 8 + coff) * 2);
                unsigned addr_l = smb + VLO_OFF * 4u + (unsigned)(vrow * 272 + (t * 8 + coff) * 2);
                unsigned vh0, vh1, vh2, vh3, vl0, vl1, vl2, vl3;
                asm volatile("ldmatrix.sync.aligned.m8n8.x4.trans.shared.b16 {%0,%1,%2,%3}, [%4];"
                             : "=r"(vh0), "=r"(vh1), "=r"(vh2), "=r"(vh3) : "r"(addr_h));
                asm volatile("ldmatrix.sync.aligned.m8n8.x4.trans.shared.b16 {%0,%1,%2,%3}, [%4];"
                             : "=r"(vl0), "=r"(vl1), "=r"(vl2), "=r"(vl3) : "r"(addr_l));
                MMA_BF16(acc[t],     ph0, ph1, ph2, ph3, vh0, vh1);
                MMA_BF16(acc[t],     ph0, ph1, ph2, ph3, vl0, vl1);
                MMA_BF16(acc[t],     pl0, pl1, pl2, pl3, vh0, vh1);
                MMA_BF16(acc[t + 1], ph0, ph1, ph2, ph3, vh2, vh3);
                MMA_BF16(acc[t + 1], ph0, ph1, ph2, ph3, vl2, vl3);
                MMA_BF16(acc[t + 1], pl0, pl1, pl2, pl3, vh2, vh3);
            }
        }
    }

    // ---- epilogue: write attn[b, qr, hw, :] ----
    float inv0 = 1.f / l0s, inv1 = 1.f / l1s;
#pragma unroll
    for (int t = 0; t < 16; ++t) {
        int col = t * 8 + 2 * c;
        float* d0 = O + (size_t)(b * S_ + qr0) * QD_ + (size_t)hw * HD_ + col;
        float* d1 = O + (size_t)(b * S_ + qr1) * QD_ + (size_t)hw * HD_ + col;
        *(float2*)d0 = make_float2(acc[t][0] * inv0, acc[t][1] * inv0);
        *(float2*)d1 = make_float2(acc[t][2] * inv1, acc[t][3] * inv1);
    }
}

// ---------------------------------------------------------------------------
extern "C" void kernel_launch(void* const* d_in, const int* in_sizes, int n_in,
                              void* d_out, int out_size)
{
    const float* x     = (const float*)d_in[0];
    const float* freqs = (const float*)d_in[1];
    const float* wq    = (const float*)d_in[2];
    const float* wk    = (const float*)d_in[3];
    const float* wv    = (const float*)d_in[4];
    const float* wo    = (const float*)d_in[5];
    float* out = (float*)d_out;

    float *q, *k, *v, *attn;
    cudaGetSymbolAddress((void**)&q,    g_q);
    cudaGetSymbolAddress((void**)&k,    g_k);
    cudaGetSymbolAddress((void**)&v,    g_v);
    cudaGetSymbolAddress((void**)&attn, g_attn);

    static int attr_set = 0;
    const int flash_smem = FLASH_SMEM_WORDS * 4;  // 139264
    if (!attr_set) {
        cudaFuncSetAttribute(gemm_bf16x3_kernel,
                             cudaFuncAttributeMaxDynamicSharedMemorySize, GEMM_SMEM);
        cudaFuncSetAttribute(gemm_qkv_fused_kernel,
                             cudaFuncAttributeMaxDynamicSharedMemorySize, GEMM_SMEM);
        cudaFuncSetAttribute(flash_bf16_kernel,
                             cudaFuncAttributeMaxDynamicSharedMemorySize, flash_smem);
        attr_set = 1;
    }

    // Fused QKV projection: 12x32 = 384 blocks (8 Q + 2 K + 2 V n-tiles of 256)
    gemm_qkv_fused_kernel<<<dim3(12, M_ / 128), 256, GEMM_SMEM>>>(
        x, wq, wk, wv, q, k, v, freqs);

    // Flash attention (GQA-packed: one block = kv-head x 32-pos window x 4 heads)
    flash_bf16_kernel<<<dim3(B_ * KVH_, S_ / 32), 256, flash_smem>>>(q, k, v, attn);

    // Output projection (bf16x3 tensor-core)
    gemm_bf16x3_kernel<<<dim3(DIM_ / 256, M_ / 128), 256, GEMM_SMEM>>>(
        attn, wo, out, DIM_, QD_, 0, freqs);
}